// round 3
// baseline (speedup 1.0000x reference)
#include <cuda_runtime.h>
#include <math.h>

#define BB 32
#define CC 512
#define LL 1024
#define NN (BB*LL)   /* 32768 tokens */

// ---------------- scratch (device globals; no allocation) ----------------
__device__ float        g_conv[(size_t)CC * NN];   // conv output [co][n], n = b*L + l   (67MB)
__device__ signed char  g_xq[(size_t)NN * CC];     // quantized activations [token][c]   (16.8MB)
__device__ float        g_stok[NN];                // per-token dequant scale = clip(max,1e-5)/127
__device__ float        g_mean[CC];
__device__ float        g_rstd[CC];
__device__ signed char  g_wq[CC * CC];             // ternary weights [o][c]
__device__ float        g_wdq;                     // weight dequant scale = clip(mean|w|,1e-5)

__device__ __forceinline__ float gelu_exact(float v) {
    return 0.5f * v * (1.0f + erff(v * 0.70710678118654752440f));
}

// ---------------- kernel 1: weight quantization ----------------
__global__ void prep_w_kernel(const float* __restrict__ w) {
    __shared__ double red[256];
    __shared__ float s_scale;
    int t = threadIdx.x;
    double s = 0.0;
    for (int i = t; i < CC * CC; i += 256) s += (double)fabsf(w[i]);
    red[t] = s; __syncthreads();
    for (int o = 128; o > 0; o >>= 1) { if (t < o) red[t] += red[t + o]; __syncthreads(); }
    if (t == 0) {
        float mean = (float)(red[0] * (1.0 / (double)(CC * CC)));
        float dq = fmaxf(mean, 1e-5f);
        g_wdq = dq;
        s_scale = 1.0f / dq;
    }
    __syncthreads();
    float sc = s_scale;
    for (int i = t; i < CC * CC; i += 256) {
        float q = rintf(w[i] * sc);              // round-half-even, matches jnp.round
        q = fminf(fmaxf(q, -1.0f), 1.0f);
        g_wq[i] = (signed char)(int)q;
    }
}

// ---------------- kernel 2: conv1d (k=3, pad 1) as fp32 tiled GEMM ----------------
// block tile: 64 co x 128 l (one batch b). 128 threads, 8x8 register tile each.
__global__ __launch_bounds__(128) void conv_kernel(const float* __restrict__ x,
                                                   const float* __restrict__ w,
                                                   const float* __restrict__ bias) {
    __shared__ float As[48 * 68];    // [ci*3+k][co]  (stride 68: float4-aligned, conflict-spread)
    __shared__ float Bs[16 * 132];   // [ci][l + 1],  covers l0-1 .. l0+128

    const int t  = threadIdx.x;
    const int tx = t & 15;           // l-group   (8 l each)
    const int ty = t >> 4;           // co-group  (8 co each)
    const int l0  = blockIdx.x * 128;
    const int co0 = blockIdx.y * 64;
    const int b   = blockIdx.z;
    const float* xb = x + (size_t)b * CC * LL;

    float acc[8][8];
    #pragma unroll
    for (int i = 0; i < 8; ++i)
        #pragma unroll
        for (int j = 0; j < 8; ++j) acc[i][j] = 0.0f;

    for (int kk = 0; kk < CC; kk += 16) {
        // W chunk: 64 co x (16 ci * 3 k); global reads coalesced along (ci,k)
        for (int i = t; i < 3072; i += 128) {
            int co = i / 48, c3 = i % 48;
            As[c3 * 68 + co] = w[(size_t)(co0 + co) * (CC * 3) + kk * 3 + c3];
        }
        // X chunk: 16 ci x 130 l (with halo, zero-padded at sequence edges)
        for (int i = t; i < 2080; i += 128) {
            int ci = i / 130, c = i % 130;
            int gl = l0 + c - 1;
            Bs[ci * 132 + c] = (gl >= 0 && gl < LL) ? xb[(size_t)(kk + ci) * LL + gl] : 0.0f;
        }
        __syncthreads();

        #pragma unroll 4
        for (int p = 0; p < 16; ++p) {
            float rb[12];
            const float* bp = &Bs[p * 132 + tx * 8];
            *(float4*)&rb[0] = *(const float4*)(bp);
            *(float4*)&rb[4] = *(const float4*)(bp + 4);
            *(float4*)&rb[8] = *(const float4*)(bp + 8);   // rb[10..11] unused padding
            #pragma unroll
            for (int k = 0; k < 3; ++k) {
                float ra[8];
                const float* ap = &As[(p * 3 + k) * 68 + ty * 8];
                *(float4*)&ra[0] = *(const float4*)(ap);
                *(float4*)&ra[4] = *(const float4*)(ap + 4);
                #pragma unroll
                for (int i = 0; i < 8; ++i)
                    #pragma unroll
                    for (int j = 0; j < 8; ++j)
                        acc[i][j] = fmaf(ra[i], rb[j + k], acc[i][j]);
            }
        }
        __syncthreads();
    }

    #pragma unroll
    for (int i = 0; i < 8; ++i) {
        int co = co0 + ty * 8 + i;
        float bv = bias[co];
        float* dst = g_conv + (size_t)co * NN + (size_t)b * LL + l0 + tx * 8;
        float4 v0, v1;
        v0.x = acc[i][0] + bv; v0.y = acc[i][1] + bv; v0.z = acc[i][2] + bv; v0.w = acc[i][3] + bv;
        v1.x = acc[i][4] + bv; v1.y = acc[i][5] + bv; v1.z = acc[i][6] + bv; v1.w = acc[i][7] + bv;
        *(float4*)dst       = v0;
        *(float4*)(dst + 4) = v1;
    }
}

// ---------------- kernel 3: BN batch stats (deterministic double reduction) ----------------
__global__ void bn_stats_kernel() {
    __shared__ double r1[256], r2[256];
    int co = blockIdx.x, t = threadIdx.x;
    const float* row = g_conv + (size_t)co * NN;
    double s = 0.0, s2 = 0.0;
    for (int i = t; i < NN; i += 256) { float v = row[i]; s += v; s2 += (double)v * (double)v; }
    r1[t] = s; r2[t] = s2; __syncthreads();
    for (int o = 128; o > 0; o >>= 1) {
        if (t < o) { r1[t] += r1[t + o]; r2[t] += r2[t + o]; }
        __syncthreads();
    }
    if (t == 0) {
        double m   = r1[0] / (double)NN;
        double var = r2[0] / (double)NN - m * m;
        g_mean[co] = (float)m;
        g_rstd[co] = (float)(1.0 / sqrt(var + 1e-5));
    }
}

// ---------------- kernel 4: BN apply + GELU + per-token int8 quant ----------------
// 16 tokens per block, 256 threads: thread (w = t>>4, n = t&15) covers co = w + 16*i.
__global__ __launch_bounds__(256) void quant_kernel(const float* __restrict__ gamma,
                                                    const float* __restrict__ beta) {
    __shared__ float s_m[CC], s_r[CC], s_g[CC], s_b[CC];
    __shared__ float pm[256];
    __shared__ float sscale[16];
    __shared__ signed char qt[16 * 520];   // 520 = 512 + 8 pad (int-aligned rows)

    int t = threadIdx.x;
    int w = t >> 4, n = t & 15;
    int n0 = blockIdx.x * 16;

    for (int i = t; i < CC; i += 256) {
        s_m[i] = g_mean[i]; s_r[i] = g_rstd[i]; s_g[i] = gamma[i]; s_b[i] = beta[i];
    }
    __syncthreads();

    float gv[32];
    float mx = 0.0f;
    #pragma unroll
    for (int i = 0; i < 32; ++i) {
        int co = w + 16 * i;
        float v = g_conv[(size_t)co * NN + n0 + n];
        v = (v - s_m[co]) * s_r[co] * s_g[co] + s_b[co];
        float g = gelu_exact(v);
        gv[i] = g;
        mx = fmaxf(mx, fabsf(g));
    }
    pm[t] = mx;
    __syncthreads();
    if (t < 16) {
        float m2 = pm[t];
        #pragma unroll
        for (int ww = 1; ww < 16; ++ww) m2 = fmaxf(m2, pm[ww * 16 + t]);
        m2 = fmaxf(m2, 1e-5f);                      // clip(max, Q_EPS)
        g_stok[n0 + t] = m2 * (1.0f / 127.0f);      // dequant multiplier
        sscale[t] = 127.0f / m2;
    }
    __syncthreads();
    float sc = sscale[n];
    #pragma unroll
    for (int i = 0; i < 32; ++i) {
        int co = w + 16 * i;
        float q = rintf(gv[i] * sc);
        q = fminf(fmaxf(q, -128.0f), 127.0f);
        qt[n * 520 + co] = (signed char)(int)q;
    }
    __syncthreads();
    // coalesced int writes: 16 tokens x 128 ints
    const int* qti = (const int*)qt;               // row stride 130 ints
    for (int lin = t; lin < 16 * 128; lin += 256) {
        int r = lin >> 7, c = lin & 127;
        ((int*)(g_xq + (size_t)(n0 + r) * CC))[c] = qti[r * 130 + c];
    }
}

// ---------------- kernel 5: int8 proj GEMM (dp4a, exact) + dequant + GELU + residual ----------------
// block tile: 64 tokens x 64 co_out, K = 512 bytes (two 256B chunks). 256 threads, 4x4 per thread.
__global__ __launch_bounds__(256) void proj_kernel(const float* __restrict__ xres,
                                                   float* __restrict__ out) {
    __shared__ int As2[64 * 68];  // [kc][token]  K-major -> conflict-free int4 loads
    __shared__ int Bs2[64 * 68];  // [kc][co]

    int t = threadIdx.x;
    int tx = t & 15, ty = t >> 4;
    int tok0 = blockIdx.x * 64;
    int co0  = blockIdx.y * 64;

    int acc[4][4];
    #pragma unroll
    for (int i = 0; i < 4; ++i)
        #pragma unroll
        for (int j = 0; j < 4; ++j) acc[i][j] = 0;

    const int* xq = (const int*)g_xq;   // 128 ints per token
    const int* wq = (const int*)g_wq;   // 128 ints per output channel

    for (int ch = 0; ch < 2; ++ch) {
        for (int lin = t; lin < 4096; lin += 256) {
            int row = lin >> 6, kc = lin & 63;
            As2[kc * 68 + row] = xq[(size_t)(tok0 + row) * 128 + ch * 64 + kc];
            Bs2[kc * 68 + row] = wq[(size_t)(co0 + row) * 128 + ch * 64 + kc];
        }
        __syncthreads();
        #pragma unroll 8
        for (int kk = 0; kk < 64; ++kk) {
            int4 a = *(const int4*)&As2[kk * 68 + tx * 4];
            int4 b = *(const int4*)&Bs2[kk * 68 + ty * 4];
            int av[4] = {a.x, a.y, a.z, a.w};
            int bv[4] = {b.x, b.y, b.z, b.w};
            #pragma unroll
            for (int ti = 0; ti < 4; ++ti)
                #pragma unroll
                for (int oi = 0; oi < 4; ++oi)
                    acc[ti][oi] = __dp4a(av[ti], bv[oi], acc[ti][oi]);
        }
        __syncthreads();
    }

    // epilogue: dequant, gelu, + residual, write [b][co][l]
    float wdq = g_wdq;
    int b  = tok0 >> 10;
    int l0 = tok0 & 1023;
    float st[4];
    #pragma unroll
    for (int ti = 0; ti < 4; ++ti) st[ti] = g_stok[tok0 + tx * 4 + ti];

    #pragma unroll
    for (int oi = 0; oi < 4; ++oi) {
        int co = co0 + ty * 4 + oi;
        size_t base = (((size_t)b * CC + co) << 10) + l0 + tx * 4;
        float4 r = *(const float4*)&xres[base];
        float4 o4;
        o4.x = gelu_exact((float)acc[0][oi] * st[0] * wdq) + r.x;
        o4.y = gelu_exact((float)acc[1][oi] * st[1] * wdq) + r.y;
        o4.z = gelu_exact((float)acc[2][oi] * st[2] * wdq) + r.z;
        o4.w = gelu_exact((float)acc[3][oi] * st[3] * wdq) + r.w;
        *(float4*)&out[base] = o4;
    }
}

// ---------------- launch ----------------
extern "C" void kernel_launch(void* const* d_in, const int* in_sizes, int n_in,
                              void* d_out, int out_size) {
    (void)in_sizes; (void)n_in; (void)out_size;
    const float* x      = (const float*)d_in[0];   // [32,512,1024]
    const float* conv_w = (const float*)d_in[1];   // [512,512,3]
    const float* conv_b = (const float*)d_in[2];   // [512]
    const float* gamma  = (const float*)d_in[3];   // [512]
    const float* beta   = (const float*)d_in[4];   // [512]
    const float* proj_w = (const float*)d_in[5];   // [512,512]
    float* out = (float*)d_out;

    prep_w_kernel<<<1, 256>>>(proj_w);
    conv_kernel<<<dim3(8, 8, 32), 128>>>(x, conv_w, conv_b);
    bn_stats_kernel<<<512, 256>>>();
    quant_kernel<<<NN / 16, 256>>>(gamma, beta);
    proj_kernel<<<dim3(NN / 64, CC / 64), 256>>>(x, out);
}

// round 5
// speedup vs baseline: 1.6196x; 1.6196x over previous
#include <cuda_runtime.h>
#include <cuda_bf16.h>
#include <math.h>
#include <stdint.h>

#define BB 32
#define CC 512
#define LL 1024
#define NN (BB*LL)   /* 32768 tokens */

// ---------------- scratch (device globals; no allocation) ----------------
__device__ __align__(16) float        g_conv[(size_t)NN * CC];      // conv out [token][co] (67MB)
__device__ __align__(16) signed char  g_xq[(size_t)NN * CC];        // int8 activations [token][c]
__device__ __align__(16) float        g_stok[NN];                   // per-token dequant scale
__device__ __align__(16) float        g_mean[CC];
__device__ __align__(16) float        g_rstd[CC];
__device__ __align__(16) signed char  g_wq[CC * CC];                // ternary proj weights [o][c]
__device__ float                      g_wdq;                        // weight dequant scale
// bf16-split packed operands for the tensor-core conv GEMM (K layout: [tap*512 + ci], hi then lo)
__device__ __align__(16) __nv_bfloat16 g_wq2[(size_t)CC * 3072];    // weights  [co][3072]
__device__ __align__(16) __nv_bfloat16 g_bq[(size_t)NN * 3072];     // activations [token][3072] (201MB)
__device__ double g_ps[64 * CC];
__device__ double g_ps2[64 * CC];

__device__ __forceinline__ float gelu_exact(float v) {
    return 0.5f * v * (1.0f + erff(v * 0.70710678118654752440f));
}

// ---------------- helpers ----------------
__device__ __forceinline__ uint32_t smem_u32(const void* p) {
    uint32_t a;
    asm("{ .reg .u64 t; cvta.to.shared.u64 t, %1; cvt.u32.u64 %0, t; }" : "=r"(a) : "l"(p));
    return a;
}
#define SWZ(o) ((o) ^ (((o) >> 3) & 0x70))

__device__ __forceinline__ void cp16(uint32_t dst, const void* src) {
    asm volatile("cp.async.cg.shared.global [%0], [%1], 16;" :: "r"(dst), "l"(src));
}
#define CP_COMMIT() asm volatile("cp.async.commit_group;" ::: "memory")
#define CP_WAIT0()  asm volatile("cp.async.wait_group 0;" ::: "memory")
#define CP_WAIT1()  asm volatile("cp.async.wait_group 1;" ::: "memory")

#define LDSM_X4(r0, r1, r2, r3, addr) \
    asm volatile("ldmatrix.sync.aligned.m8n8.x4.shared.b16 {%0,%1,%2,%3}, [%4];" \
        : "=r"(r0), "=r"(r1), "=r"(r2), "=r"(r3) : "r"(addr))

__device__ __forceinline__ void mma16816(float* d, const uint32_t* a, uint32_t b0, uint32_t b1) {
    asm volatile("mma.sync.aligned.m16n8k16.row.col.f32.bf16.bf16.f32 "
        "{%0,%1,%2,%3}, {%4,%5,%6,%7}, {%8,%9}, {%0,%1,%2,%3};"
        : "+f"(d[0]), "+f"(d[1]), "+f"(d[2]), "+f"(d[3])
        : "r"(a[0]), "r"(a[1]), "r"(a[2]), "r"(a[3]), "r"(b0), "r"(b1));
}

// ---------------- kernel: proj weight quantization (ternary) ----------------
__global__ void prep_w_kernel(const float* __restrict__ w) {
    __shared__ double red[256];
    __shared__ float s_scale;
    int t = threadIdx.x;
    double s = 0.0;
    for (int i = t; i < CC * CC; i += 256) s += (double)fabsf(w[i]);
    red[t] = s; __syncthreads();
    for (int o = 128; o > 0; o >>= 1) { if (t < o) red[t] += red[t + o]; __syncthreads(); }
    if (t == 0) {
        float mean = (float)(red[0] * (1.0 / (double)(CC * CC)));
        float dq = fmaxf(mean, 1e-5f);
        g_wdq = dq;
        s_scale = 1.0f / dq;
    }
    __syncthreads();
    float sc = s_scale;
    for (int i = t; i < CC * CC; i += 256) {
        float q = rintf(w[i] * sc);
        q = fminf(fmaxf(q, -1.0f), 1.0f);
        g_wq[i] = (signed char)(int)q;
    }
}

// ---------------- kernel: conv weight bf16-split pack ----------------
__global__ void pack_w_kernel(const float* __restrict__ w) {   // w: [co][ci][3]
    int idx = blockIdx.x * 256 + threadIdx.x;
    if (idx >= CC * 1536) return;
    int co = idx / 1536, r = idx % 1536;
    int tap = r / 512, ci = r % 512;
    float f = w[((size_t)co * CC + ci) * 3 + tap];
    __nv_bfloat16 h = __float2bfloat16(f);
    __nv_bfloat16 l = __float2bfloat16(f - __bfloat162float(h));
    g_wq2[(size_t)co * 3072 + r]        = h;
    g_wq2[(size_t)co * 3072 + 1536 + r] = l;
}

// ---------------- kernel: activation transpose + tap shift + bf16-split pack ----------------
__global__ __launch_bounds__(256) void pack_x_kernel(const float* __restrict__ x) {
    __shared__ float xs[64][132];
    int b = blockIdx.z;
    int ci0 = blockIdx.y * 64;
    int l0 = blockIdx.x * 128;
    for (int it = threadIdx.x; it < 64 * 130; it += 256) {
        int ci = it / 130, c = it % 130;
        int gl = l0 + c - 1;
        xs[ci][c] = (gl >= 0 && gl < LL) ? x[((size_t)b * CC + ci0 + ci) * LL + gl] : 0.0f;
    }
    __syncthreads();
    for (int it = threadIdx.x; it < 6144; it += 256) {
        int g = it & 7;
        int rest = it >> 3;
        int split = rest & 1;
        int rest2 = rest >> 1;
        int tap = rest2 % 3, tok = rest2 / 3;
        int lcol = tok + tap;
        __align__(16) __nv_bfloat16 v[8];
        #pragma unroll
        for (int e = 0; e < 8; ++e) {
            float f = xs[g * 8 + e][lcol];
            __nv_bfloat16 h = __float2bfloat16(f);
            v[e] = split ? __float2bfloat16(f - __bfloat162float(h)) : h;
        }
        size_t token = (size_t)b * LL + l0 + tok;
        size_t col = (size_t)split * 1536 + tap * 512 + ci0 + g * 8;
        *(uint4*)(g_bq + token * 3072 + col) = *(const uint4*)v;
    }
}

// ---------------- kernel: conv GEMM via mma.sync bf16 (3-pass split, fp32 acc) --------
// D[co 128][tok 128] = sum_K A[co][k] * B[tok][k]; 72 chunks of k64
static __device__ __forceinline__ void ld_chunk(uint32_t abuf, uint32_t bbuf,
                                                int idx, int co0, int tok0, int t) {
    int p = idx / 24, ch = idx % 24;
    int aoff = ((p == 2) ? 1536 : 0) + ch * 64;
    int boff = ((p == 1) ? 1536 : 0) + ch * 64;
    const __nv_bfloat16* ga = g_wq2 + (size_t)co0 * 3072 + aoff;
    const __nv_bfloat16* gb = g_bq  + (size_t)tok0 * 3072 + boff;
    for (int it = t; it < 1024; it += 256) {
        int row = it >> 3, c = it & 7;
        cp16(abuf + SWZ(row * 128 + c * 16), ga + (size_t)row * 3072 + c * 8);
    }
    for (int it = t; it < 1024; it += 256) {
        int row = it >> 3, c = it & 7;
        cp16(bbuf + SWZ(row * 128 + c * 16), gb + (size_t)row * 3072 + c * 8);
    }
}

__global__ __launch_bounds__(256) void conv_mma_kernel(const float* __restrict__ bias) {
    extern __shared__ char dsm_raw[];
    char* base = (char*)((((size_t)dsm_raw) + 1023) & ~(size_t)1023);
    uint32_t sb = smem_u32(base);
    uint32_t ab[2] = { sb,             sb + 32768 };
    uint32_t bb[2] = { sb + 16384,     sb + 49152 };

    int t = threadIdx.x, wid = t >> 5, lane = t & 31;
    int co0 = blockIdx.x * 128;
    int tok0 = blockIdx.y * 128;
    int wco  = (wid & 1) * 64;     // warp covers 64 co
    int wtok = (wid >> 1) * 32;    // warp covers 32 tokens

    float acc[4][4][4];
    #pragma unroll
    for (int i = 0; i < 4; ++i)
        #pragma unroll
        for (int j = 0; j < 4; ++j)
            #pragma unroll
            for (int e = 0; e < 4; ++e) acc[i][j][e] = 0.0f;

    // per-lane ldmatrix addresses (swizzle XOR mask is k-invariant)
    int g = lane >> 3, r = lane & 7;
    uint32_t ao[4], aM[4], bo[2], bM[2];
    #pragma unroll
    for (int mt = 0; mt < 4; ++mt) {
        int row = wco + mt * 16 + (g & 1) * 8 + r;
        uint32_t o = row * 128 + (g >> 1) * 16;
        aM[mt] = (o >> 3) & 0x70; ao[mt] = o;
    }
    #pragma unroll
    for (int nt = 0; nt < 2; ++nt) {
        int row = wtok + nt * 16 + (g >> 1) * 8 + r;
        uint32_t o = row * 128 + (g & 1) * 16;
        bM[nt] = (o >> 3) & 0x70; bo[nt] = o;
    }

    ld_chunk(ab[0], bb[0], 0, co0, tok0, t);
    CP_COMMIT();

    for (int i = 0; i < 72; ++i) {
        int cur = i & 1;
        if (i + 1 < 72) {
            ld_chunk(ab[cur ^ 1], bb[cur ^ 1], i + 1, co0, tok0, t);
            CP_COMMIT();
            CP_WAIT1();
        } else {
            CP_WAIT0();
        }
        __syncthreads();

        uint32_t abase = ab[cur], bbase = bb[cur];
        #pragma unroll
        for (int ks = 0; ks < 4; ++ks) {
            uint32_t A[4][4], Bf[2][4];
            #pragma unroll
            for (int mt = 0; mt < 4; ++mt)
                LDSM_X4(A[mt][0], A[mt][1], A[mt][2], A[mt][3],
                        abase + (((ao[mt] + ks * 32)) ^ aM[mt]));
            #pragma unroll
            for (int nt = 0; nt < 2; ++nt)
                LDSM_X4(Bf[nt][0], Bf[nt][1], Bf[nt][2], Bf[nt][3],
                        bbase + (((bo[nt] + ks * 32)) ^ bM[nt]));
            #pragma unroll
            for (int mt = 0; mt < 4; ++mt)
                #pragma unroll
                for (int n8 = 0; n8 < 4; ++n8)
                    mma16816(acc[mt][n8], A[mt],
                             Bf[n8 >> 1][(n8 & 1) * 2], Bf[n8 >> 1][(n8 & 1) * 2 + 1]);
        }
        __syncthreads();
    }

    // epilogue: d0/d1 -> (tok, tok+1) @ co ; d2/d3 -> (tok, tok+1) @ co+8
    #pragma unroll
    for (int mt = 0; mt < 4; ++mt) {
        int co = co0 + wco + mt * 16 + (lane >> 2);
        float bv0 = bias[co], bv1 = bias[co + 8];
        #pragma unroll
        for (int n8 = 0; n8 < 4; ++n8) {
            int tok = tok0 + wtok + n8 * 8 + (lane & 3) * 2;
            g_conv[(size_t)tok * CC + co]           = acc[mt][n8][0] + bv0;
            g_conv[(size_t)(tok + 1) * CC + co]     = acc[mt][n8][1] + bv0;
            g_conv[(size_t)tok * CC + co + 8]       = acc[mt][n8][2] + bv1;
            g_conv[(size_t)(tok + 1) * CC + co + 8] = acc[mt][n8][3] + bv1;
        }
    }
}

// ---------------- BN stats: deterministic two-stage double reduction ----------------
__global__ void bn_part_kernel() {
    int co = threadIdx.x;             // 512
    int s = blockIdx.x;               // 64 slices x 512 tokens
    double a = 0.0, b2 = 0.0;
    const float* p = g_conv + (size_t)s * 512 * CC + co;
    for (int i = 0; i < 512; ++i) {
        float v = p[(size_t)i * CC];
        a += v; b2 += (double)v * (double)v;
    }
    g_ps[s * CC + co] = a;
    g_ps2[s * CC + co] = b2;
}
__global__ void bn_fin_kernel() {
    int co = threadIdx.x;
    double a = 0.0, b2 = 0.0;
    for (int s = 0; s < 64; ++s) { a += g_ps[s * CC + co]; b2 += g_ps2[s * CC + co]; }
    double m = a / (double)NN;
    double var = b2 / (double)NN - m * m;
    g_mean[co] = (float)m;
    g_rstd[co] = (float)(1.0 / sqrt(var + 1e-5));
}

// ---------------- BN apply + GELU + per-token int8 quant (warp per token) ----------------
__global__ __launch_bounds__(256) void quant_kernel(const float* __restrict__ gamma,
                                                    const float* __restrict__ beta) {
    int t = threadIdx.x, w = t >> 5, lane = t & 31;
    size_t token = (size_t)blockIdx.x * 8 + w;
    int c0 = lane * 16;
    float vals[16];
    float mx = 0.0f;
    #pragma unroll
    for (int i = 0; i < 4; ++i) {
        float4 cv = *(const float4*)(g_conv + token * CC + c0 + i * 4);
        float4 m4 = *(const float4*)(g_mean + c0 + i * 4);
        float4 r4 = *(const float4*)(g_rstd + c0 + i * 4);
        float4 gm = *(const float4*)(gamma + c0 + i * 4);
        float4 bt = *(const float4*)(beta + c0 + i * 4);
        float a[4] = { (cv.x - m4.x) * r4.x * gm.x + bt.x,
                       (cv.y - m4.y) * r4.y * gm.y + bt.y,
                       (cv.z - m4.z) * r4.z * gm.z + bt.z,
                       (cv.w - m4.w) * r4.w * gm.w + bt.w };
        #pragma unroll
        for (int e = 0; e < 4; ++e) {
            float gg = gelu_exact(a[e]);
            vals[i * 4 + e] = gg;
            mx = fmaxf(mx, fabsf(gg));
        }
    }
    #pragma unroll
    for (int off = 16; off > 0; off >>= 1)
        mx = fmaxf(mx, __shfl_xor_sync(0xffffffff, mx, off));
    float clip = fmaxf(mx, 1e-5f);
    if (lane == 0) g_stok[token] = clip * (1.0f / 127.0f);
    float sc = 127.0f / clip;
    int pk[4];
    #pragma unroll
    for (int i = 0; i < 4; ++i) {
        int b0 = 0;
        #pragma unroll
        for (int e = 0; e < 4; ++e) {
            float q = rintf(vals[i * 4 + e] * sc);
            q = fminf(fmaxf(q, -128.0f), 127.0f);
            b0 |= ((int)q & 0xff) << (e * 8);
        }
        pk[i] = b0;
    }
    *(int4*)(g_xq + token * CC + c0) = make_int4(pk[0], pk[1], pk[2], pk[3]);
}

// ---------------- int8 proj GEMM (dp4a, exact) + dequant + GELU + residual ----------------
__global__ __launch_bounds__(256) void proj_kernel(const float* __restrict__ xres,
                                                   float* __restrict__ out) {
    __shared__ int As2[64 * 68];
    __shared__ int Bs2[64 * 68];

    int t = threadIdx.x;
    int tx = t & 15, ty = t >> 4;
    int tok0 = blockIdx.x * 64;
    int co0  = blockIdx.y * 64;

    int acc[4][4];
    #pragma unroll
    for (int i = 0; i < 4; ++i)
        #pragma unroll
        for (int j = 0; j < 4; ++j) acc[i][j] = 0;

    const int* xq = (const int*)g_xq;
    const int* wq = (const int*)g_wq;

    for (int ch = 0; ch < 2; ++ch) {
        for (int lin = t; lin < 4096; lin += 256) {
            int row = lin >> 6, kc = lin & 63;
            As2[kc * 68 + row] = xq[(size_t)(tok0 + row) * 128 + ch * 64 + kc];
            Bs2[kc * 68 + row] = wq[(size_t)(co0 + row) * 128 + ch * 64 + kc];
        }
        __syncthreads();
        #pragma unroll 8
        for (int kk = 0; kk < 64; ++kk) {
            int4 a = *(const int4*)&As2[kk * 68 + tx * 4];
            int4 b = *(const int4*)&Bs2[kk * 68 + ty * 4];
            int av[4] = { a.x, a.y, a.z, a.w };
            int bv[4] = { b.x, b.y, b.z, b.w };
            #pragma unroll
            for (int ti = 0; ti < 4; ++ti)
                #pragma unroll
                for (int oi = 0; oi < 4; ++oi)
                    acc[ti][oi] = __dp4a(av[ti], bv[oi], acc[ti][oi]);
        }
        __syncthreads();
    }

    float wdq = g_wdq;
    int b  = tok0 >> 10;
    int l0 = tok0 & 1023;
    float st[4];
    #pragma unroll
    for (int ti = 0; ti < 4; ++ti) st[ti] = g_stok[tok0 + tx * 4 + ti];

    #pragma unroll
    for (int oi = 0; oi < 4; ++oi) {
        int co = co0 + ty * 4 + oi;
        size_t base = (((size_t)b * CC + co) << 10) + l0 + tx * 4;
        float4 rr = *(const float4*)&xres[base];
        float4 o4;
        o4.x = gelu_exact((float)acc[0][oi] * st[0] * wdq) + rr.x;
        o4.y = gelu_exact((float)acc[1][oi] * st[1] * wdq) + rr.y;
        o4.z = gelu_exact((float)acc[2][oi] * st[2] * wdq) + rr.z;
        o4.w = gelu_exact((float)acc[3][oi] * st[3] * wdq) + rr.w;
        *(float4*)&out[base] = o4;
    }
}

// ---------------- launch ----------------
extern "C" void kernel_launch(void* const* d_in, const int* in_sizes, int n_in,
                              void* d_out, int out_size) {
    (void)in_sizes; (void)n_in; (void)out_size;
    const float* x      = (const float*)d_in[0];   // [32,512,1024]
    const float* conv_w = (const float*)d_in[1];   // [512,512,3]
    const float* conv_b = (const float*)d_in[2];   // [512]
    const float* gamma  = (const float*)d_in[3];   // [512]
    const float* beta   = (const float*)d_in[4];   // [512]
    const float* proj_w = (const float*)d_in[5];   // [512,512]
    float* out = (float*)d_out;

    prep_w_kernel<<<1, 256>>>(proj_w);
    pack_w_kernel<<<(CC * 1536 + 255) / 256, 256>>>(conv_w);
    pack_x_kernel<<<dim3(8, 8, 32), 256>>>(x);

    static int smem_set = 0;
    if (!smem_set) {
        cudaFuncSetAttribute(conv_mma_kernel, cudaFuncAttributeMaxDynamicSharedMemorySize, 66560);
        smem_set = 1;
    }
    conv_mma_kernel<<<dim3(4, 256), 256, 66560>>>(conv_b);

    bn_part_kernel<<<64, 512>>>();
    bn_fin_kernel<<<1, 512>>>();
    quant_kernel<<<NN / 8, 256>>>(gamma, beta);
    proj_kernel<<<dim3(NN / 64, CC / 64), 256>>>(x, out);
}

// round 7
// speedup vs baseline: 1.6576x; 1.0234x over previous
#include <cuda_runtime.h>
#include <cuda_bf16.h>
#include <math.h>
#include <stdint.h>

#define BB 32
#define CC 512
#define LL 1024
#define NN (BB*LL)   /* 32768 tokens */

// ---------------- scratch (device globals; no allocation) ----------------
__device__ __align__(16) float        g_conv[(size_t)NN * CC];      // conv out [token][co] (67MB)
__device__ __align__(16) signed char  g_xq[(size_t)NN * CC];        // int8 activations [token][c]
__device__ __align__(16) float        g_stok[NN];                   // per-token dequant scale
__device__ __align__(16) float        g_mean[CC];
__device__ __align__(16) float        g_rstd[CC];
__device__ __align__(16) signed char  g_wq[CC * CC];                // ternary proj weights [o][c]
__device__ float                      g_wdq;                        // weight dequant scale
// bf16-split packed operands for the tensor-core conv GEMM (K layout: [tap*512 + ci], hi then lo)
__device__ __align__(16) __nv_bfloat16 g_wq2[(size_t)CC * 3072];    // weights  [co][3072]
__device__ __align__(16) __nv_bfloat16 g_bq[(size_t)NN * 3072];     // activations [token][3072] (201MB)
__device__ double g_ps[64 * CC];
__device__ double g_ps2[64 * CC];

__device__ __forceinline__ float gelu_exact(float v) {
    return 0.5f * v * (1.0f + erff(v * 0.70710678118654752440f));
}

// ---------------- helpers ----------------
__device__ __forceinline__ uint32_t smem_u32(const void* p) {
    uint32_t a;
    asm("{ .reg .u64 t; cvta.to.shared.u64 t, %1; cvt.u32.u64 %0, t; }" : "=r"(a) : "l"(p));
    return a;
}
#define SWZ(o) ((o) ^ (((o) >> 3) & 0x70))

__device__ __forceinline__ void cp16(uint32_t dst, const void* src) {
    asm volatile("cp.async.cg.shared.global [%0], [%1], 16;" :: "r"(dst), "l"(src));
}
#define CP_COMMIT() asm volatile("cp.async.commit_group;" ::: "memory")
#define CP_WAIT0()  asm volatile("cp.async.wait_group 0;" ::: "memory")
#define CP_WAIT1()  asm volatile("cp.async.wait_group 1;" ::: "memory")

#define LDSM_X4(r0, r1, r2, r3, addr) \
    asm volatile("ldmatrix.sync.aligned.m8n8.x4.shared.b16 {%0,%1,%2,%3}, [%4];" \
        : "=r"(r0), "=r"(r1), "=r"(r2), "=r"(r3) : "r"(addr))

__device__ __forceinline__ void mma16816(float* d, const uint32_t* a, uint32_t b0, uint32_t b1) {
    asm volatile("mma.sync.aligned.m16n8k16.row.col.f32.bf16.bf16.f32 "
        "{%0,%1,%2,%3}, {%4,%5,%6,%7}, {%8,%9}, {%0,%1,%2,%3};"
        : "+f"(d[0]), "+f"(d[1]), "+f"(d[2]), "+f"(d[3])
        : "r"(a[0]), "r"(a[1]), "r"(a[2]), "r"(a[3]), "r"(b0), "r"(b1));
}

__device__ __forceinline__ void imma16832(int* d, const uint32_t* a, uint32_t b0, uint32_t b1) {
    asm volatile("mma.sync.aligned.m16n8k32.row.col.s32.s8.s8.s32 "
        "{%0,%1,%2,%3}, {%4,%5,%6,%7}, {%8,%9}, {%0,%1,%2,%3};"
        : "+r"(d[0]), "+r"(d[1]), "+r"(d[2]), "+r"(d[3])
        : "r"(a[0]), "r"(a[1]), "r"(a[2]), "r"(a[3]), "r"(b0), "r"(b1));
}

// ---------------- kernel: proj weight quantization (ternary) ----------------
__global__ void prep_w_kernel(const float* __restrict__ w) {
    __shared__ double red[256];
    __shared__ float s_scale;
    int t = threadIdx.x;
    double s = 0.0;
    for (int i = t; i < CC * CC; i += 256) s += (double)fabsf(w[i]);
    red[t] = s; __syncthreads();
    for (int o = 128; o > 0; o >>= 1) { if (t < o) red[t] += red[t + o]; __syncthreads(); }
    if (t == 0) {
        float mean = (float)(red[0] * (1.0 / (double)(CC * CC)));
        float dq = fmaxf(mean, 1e-5f);
        g_wdq = dq;
        s_scale = 1.0f / dq;
    }
    __syncthreads();
    float sc = s_scale;
    for (int i = t; i < CC * CC; i += 256) {
        float q = rintf(w[i] * sc);
        q = fminf(fmaxf(q, -1.0f), 1.0f);
        g_wq[i] = (signed char)(int)q;
    }
}

// ---------------- kernel: conv weight bf16-split pack ----------------
__global__ void pack_w_kernel(const float* __restrict__ w) {   // w: [co][ci][3]
    int idx = blockIdx.x * 256 + threadIdx.x;
    if (idx >= CC * 1536) return;
    int co = idx / 1536, r = idx % 1536;
    int tap = r / 512, ci = r % 512;
    float f = w[((size_t)co * CC + ci) * 3 + tap];
    __nv_bfloat16 h = __float2bfloat16(f);
    __nv_bfloat16 l = __float2bfloat16(f - __bfloat162float(h));
    g_wq2[(size_t)co * 3072 + r]        = h;
    g_wq2[(size_t)co * 3072 + 1536 + r] = l;
}

// ---------------- kernel: activation transpose + tap shift + bf16-split pack ----------------
__global__ __launch_bounds__(256) void pack_x_kernel(const float* __restrict__ x) {
    __shared__ float xs[64][132];
    int b = blockIdx.z;
    int ci0 = blockIdx.y * 64;
    int l0 = blockIdx.x * 128;
    for (int it = threadIdx.x; it < 64 * 130; it += 256) {
        int ci = it / 130, c = it % 130;
        int gl = l0 + c - 1;
        xs[ci][c] = (gl >= 0 && gl < LL) ? x[((size_t)b * CC + ci0 + ci) * LL + gl] : 0.0f;
    }
    __syncthreads();
    for (int it = threadIdx.x; it < 6144; it += 256) {
        int g = it & 7;
        int rest = it >> 3;
        int split = rest & 1;
        int rest2 = rest >> 1;
        int tap = rest2 % 3, tok = rest2 / 3;
        int lcol = tok + tap;
        __align__(16) __nv_bfloat16 v[8];
        #pragma unroll
        for (int e = 0; e < 8; ++e) {
            float f = xs[g * 8 + e][lcol];
            __nv_bfloat16 h = __float2bfloat16(f);
            v[e] = split ? __float2bfloat16(f - __bfloat162float(h)) : h;
        }
        size_t token = (size_t)b * LL + l0 + tok;
        size_t col = (size_t)split * 1536 + tap * 512 + ci0 + g * 8;
        *(uint4*)(g_bq + token * 3072 + col) = *(const uint4*)v;
    }
}

// ---------------- kernel: conv GEMM via mma.sync bf16 (3-pass split, fp32 acc) --------
static __device__ __forceinline__ void ld_chunk(uint32_t abuf, uint32_t bbuf,
                                                int idx, int co0, int tok0, int t) {
    int p = idx / 24, ch = idx % 24;
    int aoff = ((p == 2) ? 1536 : 0) + ch * 64;
    int boff = ((p == 1) ? 1536 : 0) + ch * 64;
    const __nv_bfloat16* ga = g_wq2 + (size_t)co0 * 3072 + aoff;
    const __nv_bfloat16* gb = g_bq  + (size_t)tok0 * 3072 + boff;
    for (int it = t; it < 1024; it += 256) {
        int row = it >> 3, c = it & 7;
        cp16(abuf + SWZ(row * 128 + c * 16), ga + (size_t)row * 3072 + c * 8);
    }
    for (int it = t; it < 1024; it += 256) {
        int row = it >> 3, c = it & 7;
        cp16(bbuf + SWZ(row * 128 + c * 16), gb + (size_t)row * 3072 + c * 8);
    }
}

__global__ __launch_bounds__(256) void conv_mma_kernel(const float* __restrict__ bias) {
    extern __shared__ char dsm_raw[];
    char* base = (char*)((((size_t)dsm_raw) + 1023) & ~(size_t)1023);
    uint32_t sb = smem_u32(base);
    uint32_t ab[2] = { sb,             sb + 32768 };
    uint32_t bb[2] = { sb + 16384,     sb + 49152 };

    int t = threadIdx.x, wid = t >> 5, lane = t & 31;
    int co0 = blockIdx.x * 128;
    int tok0 = blockIdx.y * 128;
    int wco  = (wid & 1) * 64;     // warp covers 64 co
    int wtok = (wid >> 1) * 32;    // warp covers 32 tokens

    float acc[4][4][4];
    #pragma unroll
    for (int i = 0; i < 4; ++i)
        #pragma unroll
        for (int j = 0; j < 4; ++j)
            #pragma unroll
            for (int e = 0; e < 4; ++e) acc[i][j][e] = 0.0f;

    int g = lane >> 3, r = lane & 7;
    uint32_t ao[4], aM[4], bo[2], bM[2];
    #pragma unroll
    for (int mt = 0; mt < 4; ++mt) {
        int row = wco + mt * 16 + (g & 1) * 8 + r;
        uint32_t o = row * 128 + (g >> 1) * 16;
        aM[mt] = (o >> 3) & 0x70; ao[mt] = o;
    }
    #pragma unroll
    for (int nt = 0; nt < 2; ++nt) {
        int row = wtok + nt * 16 + (g >> 1) * 8 + r;
        uint32_t o = row * 128 + (g & 1) * 16;
        bM[nt] = (o >> 3) & 0x70; bo[nt] = o;
    }

    ld_chunk(ab[0], bb[0], 0, co0, tok0, t);
    CP_COMMIT();

    for (int i = 0; i < 72; ++i) {
        int cur = i & 1;
        if (i + 1 < 72) {
            ld_chunk(ab[cur ^ 1], bb[cur ^ 1], i + 1, co0, tok0, t);
            CP_COMMIT();
            CP_WAIT1();
        } else {
            CP_WAIT0();
        }
        __syncthreads();

        uint32_t abase = ab[cur], bbase = bb[cur];
        #pragma unroll
        for (int ks = 0; ks < 4; ++ks) {
            uint32_t A[4][4], Bf[2][4];
            #pragma unroll
            for (int mt = 0; mt < 4; ++mt)
                LDSM_X4(A[mt][0], A[mt][1], A[mt][2], A[mt][3],
                        abase + (((ao[mt] + ks * 32)) ^ aM[mt]));
            #pragma unroll
            for (int nt = 0; nt < 2; ++nt)
                LDSM_X4(Bf[nt][0], Bf[nt][1], Bf[nt][2], Bf[nt][3],
                        bbase + (((bo[nt] + ks * 32)) ^ bM[nt]));
            #pragma unroll
            for (int mt = 0; mt < 4; ++mt)
                #pragma unroll
                for (int n8 = 0; n8 < 4; ++n8)
                    mma16816(acc[mt][n8], A[mt],
                             Bf[n8 >> 1][(n8 & 1) * 2], Bf[n8 >> 1][(n8 & 1) * 2 + 1]);
        }
        __syncthreads();
    }

    #pragma unroll
    for (int mt = 0; mt < 4; ++mt) {
        int co = co0 + wco + mt * 16 + (lane >> 2);
        float bv0 = bias[co], bv1 = bias[co + 8];
        #pragma unroll
        for (int n8 = 0; n8 < 4; ++n8) {
            int tok = tok0 + wtok + n8 * 8 + (lane & 3) * 2;
            g_conv[(size_t)tok * CC + co]           = acc[mt][n8][0] + bv0;
            g_conv[(size_t)(tok + 1) * CC + co]     = acc[mt][n8][1] + bv0;
            g_conv[(size_t)tok * CC + co + 8]       = acc[mt][n8][2] + bv1;
            g_conv[(size_t)(tok + 1) * CC + co + 8] = acc[mt][n8][3] + bv1;
        }
    }
}

// ---------------- BN stats: deterministic two-stage double reduction ----------------
__global__ void bn_part_kernel() {
    int co = threadIdx.x;             // 512
    int s = blockIdx.x;               // 64 slices x 512 tokens
    double a = 0.0, b2 = 0.0;
    const float* p = g_conv + (size_t)s * 512 * CC + co;
    for (int i = 0; i < 512; ++i) {
        float v = p[(size_t)i * CC];
        a += v; b2 += (double)v * (double)v;
    }
    g_ps[s * CC + co] = a;
    g_ps2[s * CC + co] = b2;
}
__global__ void bn_fin_kernel() {
    int co = threadIdx.x;
    double a = 0.0, b2 = 0.0;
    for (int s = 0; s < 64; ++s) { a += g_ps[s * CC + co]; b2 += g_ps2[s * CC + co]; }
    double m = a / (double)NN;
    double var = b2 / (double)NN - m * m;
    g_mean[co] = (float)m;
    g_rstd[co] = (float)(1.0 / sqrt(var + 1e-5));
}

// ---------------- BN apply + GELU + per-token int8 quant (warp per token) ----------------
__global__ __launch_bounds__(256) void quant_kernel(const float* __restrict__ gamma,
                                                    const float* __restrict__ beta) {
    int t = threadIdx.x, w = t >> 5, lane = t & 31;
    size_t token = (size_t)blockIdx.x * 8 + w;
    int c0 = lane * 16;
    float vals[16];
    float mx = 0.0f;
    #pragma unroll
    for (int i = 0; i < 4; ++i) {
        float4 cv = *(const float4*)(g_conv + token * CC + c0 + i * 4);
        float4 m4 = *(const float4*)(g_mean + c0 + i * 4);
        float4 r4 = *(const float4*)(g_rstd + c0 + i * 4);
        float4 gm = *(const float4*)(gamma + c0 + i * 4);
        float4 bt = *(const float4*)(beta + c0 + i * 4);
        float a[4] = { (cv.x - m4.x) * r4.x * gm.x + bt.x,
                       (cv.y - m4.y) * r4.y * gm.y + bt.y,
                       (cv.z - m4.z) * r4.z * gm.z + bt.z,
                       (cv.w - m4.w) * r4.w * gm.w + bt.w };
        #pragma unroll
        for (int e = 0; e < 4; ++e) {
            float gg = gelu_exact(a[e]);
            vals[i * 4 + e] = gg;
            mx = fmaxf(mx, fabsf(gg));
        }
    }
    #pragma unroll
    for (int off = 16; off > 0; off >>= 1)
        mx = fmaxf(mx, __shfl_xor_sync(0xffffffff, mx, off));
    float clip = fmaxf(mx, 1e-5f);
    if (lane == 0) g_stok[token] = clip * (1.0f / 127.0f);
    float sc = 127.0f / clip;
    int pk[4];
    #pragma unroll
    for (int i = 0; i < 4; ++i) {
        int b0 = 0;
        #pragma unroll
        for (int e = 0; e < 4; ++e) {
            float q = rintf(vals[i * 4 + e] * sc);
            q = fminf(fmaxf(q, -128.0f), 127.0f);
            b0 |= ((int)q & 0xff) << (e * 8);
        }
        pk[i] = b0;
    }
    *(int4*)(g_xq + token * CC + c0) = make_int4(pk[0], pk[1], pk[2], pk[3]);
}

// ---------------- int8 proj GEMM via IMMA (exact) + dequant + GELU + residual -------
// D[tok 128][co 128] = sum_{c=0..511} xq[tok][c] * wq[co][c]
static __device__ __forceinline__ void ld_chunk_p(uint32_t abuf, uint32_t bbuf,
                                                  int idx, int tok0, int co0, int t) {
    const signed char* ga = g_xq + (size_t)tok0 * 512 + idx * 128;
    const signed char* gb = g_wq + (size_t)co0 * 512 + idx * 128;
    for (int it = t; it < 1024; it += 256) {
        int row = it >> 3, c = it & 7;
        cp16(abuf + SWZ(row * 128 + c * 16), ga + (size_t)row * 512 + c * 16);
    }
    for (int it = t; it < 1024; it += 256) {
        int row = it >> 3, c = it & 7;
        cp16(bbuf + SWZ(row * 128 + c * 16), gb + (size_t)row * 512 + c * 16);
    }
}

__global__ __launch_bounds__(256) void proj_mma_kernel(const float* __restrict__ xres,
                                                       float* __restrict__ out) {
    extern __shared__ char dsm_raw[];
    char* base = (char*)((((size_t)dsm_raw) + 1023) & ~(size_t)1023);
    uint32_t sb = smem_u32(base);
    uint32_t ab[2] = { sb,             sb + 32768 };
    uint32_t bb[2] = { sb + 16384,     sb + 49152 };

    int t = threadIdx.x, wid = t >> 5, lane = t & 31;
    int co0  = blockIdx.x * 128;
    int tok0 = blockIdx.y * 128;
    int wtok = (wid & 1) * 64;     // warp covers 64 tokens (m)
    int wco  = (wid >> 1) * 32;    // warp covers 32 co (n)

    int acc[4][4][4];
    #pragma unroll
    for (int i = 0; i < 4; ++i)
        #pragma unroll
        for (int j = 0; j < 4; ++j)
            #pragma unroll
            for (int e = 0; e < 4; ++e) acc[i][j][e] = 0;

    int g = lane >> 3, r = lane & 7;
    uint32_t ao[4], aM[4], bo[2], bM[2];
    #pragma unroll
    for (int mt = 0; mt < 4; ++mt) {
        int row = wtok + mt * 16 + (g & 1) * 8 + r;
        uint32_t o = row * 128 + (g >> 1) * 16;
        aM[mt] = (o >> 3) & 0x70; ao[mt] = o;
    }
    #pragma unroll
    for (int nt = 0; nt < 2; ++nt) {
        int row = wco + nt * 16 + (g >> 1) * 8 + r;
        uint32_t o = row * 128 + (g & 1) * 16;
        bM[nt] = (o >> 3) & 0x70; bo[nt] = o;
    }

    ld_chunk_p(ab[0], bb[0], 0, tok0, co0, t);
    CP_COMMIT();

    for (int i = 0; i < 4; ++i) {
        int cur = i & 1;
        if (i + 1 < 4) {
            ld_chunk_p(ab[cur ^ 1], bb[cur ^ 1], i + 1, tok0, co0, t);
            CP_COMMIT();
            CP_WAIT1();
        } else {
            CP_WAIT0();
        }
        __syncthreads();

        uint32_t abase = ab[cur], bbase = bb[cur];
        #pragma unroll
        for (int ks = 0; ks < 4; ++ks) {          // k32 steps: 32 bytes each
            uint32_t A[4][4], Bf[2][4];
            #pragma unroll
            for (int mt = 0; mt < 4; ++mt)
                LDSM_X4(A[mt][0], A[mt][1], A[mt][2], A[mt][3],
                        abase + (((ao[mt] + ks * 32)) ^ aM[mt]));
            #pragma unroll
            for (int nt = 0; nt < 2; ++nt)
                LDSM_X4(Bf[nt][0], Bf[nt][1], Bf[nt][2], Bf[nt][3],
                        bbase + (((bo[nt] + ks * 32)) ^ bM[nt]));
            #pragma unroll
            for (int mt = 0; mt < 4; ++mt)
                #pragma unroll
                for (int n8 = 0; n8 < 4; ++n8)
                    imma16832(acc[mt][n8], A[mt],
                              Bf[n8 >> 1][(n8 & 1) * 2], Bf[n8 >> 1][(n8 & 1) * 2 + 1]);
        }
        __syncthreads();
    }

    // epilogue: acc[mt][n8] = { (tokA,co), (tokA,co+1), (tokB,co), (tokB,co+1) }
    float wdq = g_wdq;
    #pragma unroll
    for (int mt = 0; mt < 4; ++mt) {
        int tokA = tok0 + wtok + mt * 16 + (lane >> 2);
        int tokB = tokA + 8;
        float sA = g_stok[tokA] * wdq;
        float sB = g_stok[tokB] * wdq;
        int bA = tokA >> 10, lA = tokA & 1023;
        int bB = tokB >> 10, lB = tokB & 1023;
        #pragma unroll
        for (int n8 = 0; n8 < 4; ++n8) {
            int co = co0 + wco + n8 * 8 + (lane & 3) * 2;
            size_t iA0 = (((size_t)bA * CC + co) << 10) + lA;
            size_t iA1 = iA0 + (1 << 10);
            size_t iB0 = (((size_t)bB * CC + co) << 10) + lB;
            size_t iB1 = iB0 + (1 << 10);
            out[iA0] = gelu_exact((float)acc[mt][n8][0] * sA) + xres[iA0];
            out[iA1] = gelu_exact((float)acc[mt][n8][1] * sA) + xres[iA1];
            out[iB0] = gelu_exact((float)acc[mt][n8][2] * sB) + xres[iB0];
            out[iB1] = gelu_exact((float)acc[mt][n8][3] * sB) + xres[iB1];
        }
    }
}

// ---------------- launch ----------------
extern "C" void kernel_launch(void* const* d_in, const int* in_sizes, int n_in,
                              void* d_out, int out_size) {
    (void)in_sizes; (void)n_in; (void)out_size;
    const float* x      = (const float*)d_in[0];   // [32,512,1024]
    const float* conv_w = (const float*)d_in[1];   // [512,512,3]
    const float* conv_b = (const float*)d_in[2];   // [512]
    const float* gamma  = (const float*)d_in[3];   // [512]
    const float* beta   = (const float*)d_in[4];   // [512]
    const float* proj_w = (const float*)d_in[5];   // [512,512]
    float* out = (float*)d_out;

    static int smem_set = 0;
    if (!smem_set) {
        cudaFuncSetAttribute(conv_mma_kernel, cudaFuncAttributeMaxDynamicSharedMemorySize, 66560);
        cudaFuncSetAttribute(proj_mma_kernel, cudaFuncAttributeMaxDynamicSharedMemorySize, 66560);
        smem_set = 1;
    }

    prep_w_kernel<<<1, 256>>>(proj_w);
    pack_w_kernel<<<(CC * 1536 + 255) / 256, 256>>>(conv_w);
    pack_x_kernel<<<dim3(8, 8, 32), 256>>>(x);

    conv_mma_kernel<<<dim3(4, 256), 256, 66560>>>(conv_b);

    bn_part_kernel<<<64, 512>>>();
    bn_fin_kernel<<<1, 512>>>();
    quant_kernel<<<NN / 8, 256>>>(gamma, beta);

    proj_mma_kernel<<<dim3(4, 256), 256, 66560>>>(x, out);
}

// round 8
// speedup vs baseline: 2.2137x; 1.3355x over previous
#include <cuda_runtime.h>
#include <cuda_bf16.h>
#include <math.h>
#include <stdint.h>

#define BB 32
#define CC 512
#define LL 1024
#define NN (BB*LL)   /* 32768 tokens */
#define BROWS (BB * (LL + 2))   /* 32*1026 guard-row layout */

// ---------------- scratch (device globals; no allocation) ----------------
__device__ __align__(16) float        g_conv[(size_t)NN * CC];      // conv out [token][co] (67MB)
__device__ __align__(16) signed char  g_xq[(size_t)NN * CC];        // int8 activations [token][c]
__device__ __align__(16) float        g_stok[NN];                   // per-token dequant scale
__device__ __align__(16) float        g_mean[CC];
__device__ __align__(16) float        g_rstd[CC];
__device__ __align__(16) signed char  g_wq[CC * CC];                // ternary proj weights [o][c]
__device__ float                      g_wdq;                        // weight dequant scale
// conv GEMM operands, bf16 2-term split
__device__ __align__(16) __nv_bfloat16 g_wq2[(size_t)CC * 3072];    // weights [co][(split?1536:0)+tap*512+ci]
// activations: row = b*1026 + 1 + l (rows b*1026 and b*1026+1025 are zero guards)
// cols: [0:512) hi-split of x[b][ci][l], [512:1024) lo-split
__device__ __align__(16) __nv_bfloat16 g_bq[(size_t)BROWS * 1024];  // 67MB
__device__ double g_ps[64 * CC];
__device__ double g_ps2[64 * CC];
__device__ double g_wsum[64];

__device__ __forceinline__ float gelu_exact(float v) {
    return 0.5f * v * (1.0f + erff(v * 0.70710678118654752440f));
}

// ---------------- helpers ----------------
__device__ __forceinline__ uint32_t smem_u32(const void* p) {
    uint32_t a;
    asm("{ .reg .u64 t; cvta.to.shared.u64 t, %1; cvt.u32.u64 %0, t; }" : "=r"(a) : "l"(p));
    return a;
}
#define SWZ(o) ((o) ^ (((o) >> 3) & 0x70))

__device__ __forceinline__ void cp16(uint32_t dst, const void* src) {
    asm volatile("cp.async.cg.shared.global [%0], [%1], 16;" :: "r"(dst), "l"(src));
}
#define CP_COMMIT() asm volatile("cp.async.commit_group;" ::: "memory")
#define CP_WAIT0()  asm volatile("cp.async.wait_group 0;" ::: "memory")
#define CP_WAIT1()  asm volatile("cp.async.wait_group 1;" ::: "memory")

#define LDSM_X4(r0, r1, r2, r3, addr) \
    asm volatile("ldmatrix.sync.aligned.m8n8.x4.shared.b16 {%0,%1,%2,%3}, [%4];" \
        : "=r"(r0), "=r"(r1), "=r"(r2), "=r"(r3) : "r"(addr))

__device__ __forceinline__ void mma16816(float* d, const uint32_t* a, uint32_t b0, uint32_t b1) {
    asm volatile("mma.sync.aligned.m16n8k16.row.col.f32.bf16.bf16.f32 "
        "{%0,%1,%2,%3}, {%4,%5,%6,%7}, {%8,%9}, {%0,%1,%2,%3};"
        : "+f"(d[0]), "+f"(d[1]), "+f"(d[2]), "+f"(d[3])
        : "r"(a[0]), "r"(a[1]), "r"(a[2]), "r"(a[3]), "r"(b0), "r"(b1));
}

__device__ __forceinline__ void imma16832(int* d, const uint32_t* a, uint32_t b0, uint32_t b1) {
    asm volatile("mma.sync.aligned.m16n8k32.row.col.s32.s8.s8.s32 "
        "{%0,%1,%2,%3}, {%4,%5,%6,%7}, {%8,%9}, {%0,%1,%2,%3};"
        : "+r"(d[0]), "+r"(d[1]), "+r"(d[2]), "+r"(d[3])
        : "r"(a[0]), "r"(a[1]), "r"(a[2]), "r"(a[3]), "r"(b0), "r"(b1));
}

// ---------------- proj weight quant: partial -> fin -> quantize ----------------
__global__ void prep_part_kernel(const float* __restrict__ w) {
    __shared__ double red[256];
    int t = threadIdx.x;
    int base = blockIdx.x * 4096;
    double s = 0.0;
    #pragma unroll 4
    for (int i = t; i < 4096; i += 256) s += (double)fabsf(w[base + i]);
    red[t] = s; __syncthreads();
    for (int o = 128; o > 0; o >>= 1) { if (t < o) red[t] += red[t + o]; __syncthreads(); }
    if (t == 0) g_wsum[blockIdx.x] = red[0];
}
__global__ void prep_fin_kernel() {
    __shared__ double red[64];
    int t = threadIdx.x;
    red[t] = g_wsum[t]; __syncthreads();
    for (int o = 32; o > 0; o >>= 1) { if (t < o) red[t] += red[t + o]; __syncthreads(); }
    if (t == 0) {
        float mean = (float)(red[0] * (1.0 / (double)(CC * CC)));
        g_wdq = fmaxf(mean, 1e-5f);
    }
}
__global__ void prep_quant_kernel(const float* __restrict__ w) {
    int i = blockIdx.x * 1024 + threadIdx.x;
    float sc = 1.0f / g_wdq;
    #pragma unroll
    for (int e = 0; e < 4; ++e) {
        int idx = i + e * 256;
        float q = rintf(w[idx] * sc);
        q = fminf(fmaxf(q, -1.0f), 1.0f);
        g_wq[idx] = (signed char)(int)q;
    }
}

// ---------------- conv weight bf16-split pack ----------------
__global__ void pack_w_kernel(const float* __restrict__ w) {   // w: [co][ci][3]
    int idx = blockIdx.x * 256 + threadIdx.x;
    if (idx >= CC * 1536) return;
    int co = idx / 1536, r = idx % 1536;
    int tap = r / 512, ci = r % 512;
    float f = w[((size_t)co * CC + ci) * 3 + tap];
    __nv_bfloat16 h = __float2bfloat16(f);
    __nv_bfloat16 l = __float2bfloat16(f - __bfloat162float(h));
    g_wq2[(size_t)co * 3072 + r]        = h;
    g_wq2[(size_t)co * 3072 + 1536 + r] = l;
}

// ---------------- activation transpose + bf16-split pack (guard-row layout) --------
__global__ __launch_bounds__(256) void pack_x_kernel(const float* __restrict__ x) {
    __shared__ float xs[128 * 65];    // [l][ci], pad 65 -> conflict-free STS, ~2-way LDS
    int b   = blockIdx.z;
    int ci0 = blockIdx.y * 64;
    int l0  = blockIdx.x * 128;
    int t = threadIdx.x;

    for (int it = t; it < 64 * 128; it += 256) {
        int ci = it >> 7, c = it & 127;
        xs[c * 65 + ci] = x[((size_t)b * CC + ci0 + ci) * LL + l0 + c];
    }
    __syncthreads();

    for (int it = t; it < 1024; it += 256) {
        int tok = it >> 3, g = it & 7;
        __align__(16) __nv_bfloat16 hi[8], lo[8];
        #pragma unroll
        for (int e = 0; e < 8; ++e) {
            float f = xs[tok * 65 + g * 8 + e];
            __nv_bfloat16 h = __float2bfloat16(f);
            hi[e] = h;
            lo[e] = __float2bfloat16(f - __bfloat162float(h));
        }
        size_t row = (size_t)b * 1026 + 1 + l0 + tok;
        *(uint4*)(g_bq + row * 1024 + ci0 + g * 8)       = *(const uint4*)hi;
        *(uint4*)(g_bq + row * 1024 + 512 + ci0 + g * 8) = *(const uint4*)lo;
    }

    // zero guard rows (each ci0-block zeroes its 64-col slice, hi+lo)
    if (l0 == 0 && t < 16) {
        size_t row = (size_t)b * 1026;
        int col = (t >> 3) * 512 + ci0 + (t & 7) * 8;
        *(uint4*)(g_bq + row * 1024 + col) = make_uint4(0, 0, 0, 0);
    }
    if (l0 == (LL - 128) && t < 16) {
        size_t row = (size_t)b * 1026 + 1025;
        int col = (t >> 3) * 512 + ci0 + (t & 7) * 8;
        *(uint4*)(g_bq + row * 1024 + col) = make_uint4(0, 0, 0, 0);
    }
}

// ---------------- conv GEMM via mma.sync bf16 (3-pass split, fp32 acc) --------
// 72 chunks: p in {hi*hi, hi_a*lo_b, lo_a*hi_b}, ch = tap*8 + ci_chunk
static __device__ __forceinline__ void ld_chunk(uint32_t abuf, uint32_t bbuf,
                                                int idx, int co0, int browb, int t) {
    int p = idx / 24, ch = idx % 24;
    int tap = ch >> 3, cic = ch & 7;
    const __nv_bfloat16* ga = g_wq2 + (size_t)co0 * 3072 + ((p == 2) ? 1536 : 0) + ch * 64;
    const __nv_bfloat16* gb = g_bq + (size_t)(browb + tap) * 1024
                                   + ((p == 1) ? 512 : 0) + cic * 64;
    for (int it = t; it < 1024; it += 256) {
        int row = it >> 3, c = it & 7;
        cp16(abuf + SWZ(row * 128 + c * 16), ga + (size_t)row * 3072 + c * 8);
    }
    for (int it = t; it < 1024; it += 256) {
        int row = it >> 3, c = it & 7;
        cp16(bbuf + SWZ(row * 128 + c * 16), gb + (size_t)row * 1024 + c * 8);
    }
}

__global__ __launch_bounds__(256) void conv_mma_kernel(const float* __restrict__ bias) {
    extern __shared__ char dsm_raw[];
    char* base = (char*)((((size_t)dsm_raw) + 1023) & ~(size_t)1023);
    uint32_t sb = smem_u32(base);
    uint32_t ab[2] = { sb,             sb + 32768 };
    uint32_t bb[2] = { sb + 16384,     sb + 49152 };

    int t = threadIdx.x, wid = t >> 5, lane = t & 31;
    int co0 = blockIdx.x * 128;
    int tok0 = blockIdx.y * 128;
    int bidx = tok0 >> 10;
    int l0 = tok0 & 1023;
    int browb = bidx * 1026 + l0;      // row for (l, tap): browb + (l - l0) ... + tap
    int wco  = (wid & 1) * 64;         // warp covers 64 co (m)
    int wtok = (wid >> 1) * 32;        // warp covers 32 tokens (n)

    float acc[4][4][4];
    #pragma unroll
    for (int i = 0; i < 4; ++i)
        #pragma unroll
        for (int j = 0; j < 4; ++j)
            #pragma unroll
            for (int e = 0; e < 4; ++e) acc[i][j][e] = 0.0f;

    int g = lane >> 3, r = lane & 7;
    uint32_t ao[4], aM[4], bo[2], bM[2];
    #pragma unroll
    for (int mt = 0; mt < 4; ++mt) {
        int row = wco + mt * 16 + (g & 1) * 8 + r;
        uint32_t o = row * 128 + (g >> 1) * 16;
        aM[mt] = (o >> 3) & 0x70; ao[mt] = o;
    }
    #pragma unroll
    for (int nt = 0; nt < 2; ++nt) {
        int row = wtok + nt * 16 + (g >> 1) * 8 + r;
        uint32_t o = row * 128 + (g & 1) * 16;
        bM[nt] = (o >> 3) & 0x70; bo[nt] = o;
    }

    ld_chunk(ab[0], bb[0], 0, co0, browb, t);
    CP_COMMIT();

    for (int i = 0; i < 72; ++i) {
        int cur = i & 1;
        if (i + 1 < 72) {
            ld_chunk(ab[cur ^ 1], bb[cur ^ 1], i + 1, co0, browb, t);
            CP_COMMIT();
            CP_WAIT1();
        } else {
            CP_WAIT0();
        }
        __syncthreads();

        uint32_t abase = ab[cur], bbase = bb[cur];
        #pragma unroll
        for (int ks = 0; ks < 4; ++ks) {
            uint32_t A[4][4], Bf[2][4];
            #pragma unroll
            for (int mt = 0; mt < 4; ++mt)
                LDSM_X4(A[mt][0], A[mt][1], A[mt][2], A[mt][3],
                        abase + (((ao[mt] + ks * 32)) ^ aM[mt]));
            #pragma unroll
            for (int nt = 0; nt < 2; ++nt)
                LDSM_X4(Bf[nt][0], Bf[nt][1], Bf[nt][2], Bf[nt][3],
                        bbase + (((bo[nt] + ks * 32)) ^ bM[nt]));
            #pragma unroll
            for (int mt = 0; mt < 4; ++mt)
                #pragma unroll
                for (int n8 = 0; n8 < 4; ++n8)
                    mma16816(acc[mt][n8], A[mt],
                             Bf[n8 >> 1][(n8 & 1) * 2], Bf[n8 >> 1][(n8 & 1) * 2 + 1]);
        }
        __syncthreads();
    }

    #pragma unroll
    for (int mt = 0; mt < 4; ++mt) {
        int co = co0 + wco + mt * 16 + (lane >> 2);
        float bv0 = bias[co], bv1 = bias[co + 8];
        #pragma unroll
        for (int n8 = 0; n8 < 4; ++n8) {
            int tok = tok0 + wtok + n8 * 8 + (lane & 3) * 2;
            g_conv[(size_t)tok * CC + co]           = acc[mt][n8][0] + bv0;
            g_conv[(size_t)(tok + 1) * CC + co]     = acc[mt][n8][1] + bv0;
            g_conv[(size_t)tok * CC + co + 8]       = acc[mt][n8][2] + bv1;
            g_conv[(size_t)(tok + 1) * CC + co + 8] = acc[mt][n8][3] + bv1;
        }
    }
}

// ---------------- BN stats: deterministic two-stage double reduction ----------------
__global__ void bn_part_kernel() {
    int co = threadIdx.x;             // 512
    int s = blockIdx.x;               // 64 slices x 512 tokens
    double a = 0.0, b2 = 0.0;
    const float* p = g_conv + (size_t)s * 512 * CC + co;
    #pragma unroll 4
    for (int i = 0; i < 512; ++i) {
        float v = p[(size_t)i * CC];
        a += v; b2 += (double)v * (double)v;
    }
    g_ps[s * CC + co] = a;
    g_ps2[s * CC + co] = b2;
}
__global__ void bn_fin_kernel() {
    int co = threadIdx.x;
    double a = 0.0, b2 = 0.0;
    #pragma unroll 4
    for (int s = 0; s < 64; ++s) { a += g_ps[s * CC + co]; b2 += g_ps2[s * CC + co]; }
    double m = a / (double)NN;
    double var = b2 / (double)NN - m * m;
    g_mean[co] = (float)m;
    g_rstd[co] = (float)(1.0 / sqrt(var + 1e-5));
}

// ---------------- BN apply + GELU + per-token int8 quant (warp per token) ----------------
__global__ __launch_bounds__(256) void quant_kernel(const float* __restrict__ gamma,
                                                    const float* __restrict__ beta) {
    int t = threadIdx.x, w = t >> 5, lane = t & 31;
    size_t token = (size_t)blockIdx.x * 8 + w;
    int c0 = lane * 16;
    float vals[16];
    float mx = 0.0f;
    #pragma unroll
    for (int i = 0; i < 4; ++i) {
        float4 cv = *(const float4*)(g_conv + token * CC + c0 + i * 4);
        float4 m4 = *(const float4*)(g_mean + c0 + i * 4);
        float4 r4 = *(const float4*)(g_rstd + c0 + i * 4);
        float4 gm = *(const float4*)(gamma + c0 + i * 4);
        float4 bt = *(const float4*)(beta + c0 + i * 4);
        float a[4] = { (cv.x - m4.x) * r4.x * gm.x + bt.x,
                       (cv.y - m4.y) * r4.y * gm.y + bt.y,
                       (cv.z - m4.z) * r4.z * gm.z + bt.z,
                       (cv.w - m4.w) * r4.w * gm.w + bt.w };
        #pragma unroll
        for (int e = 0; e < 4; ++e) {
            float gg = gelu_exact(a[e]);
            vals[i * 4 + e] = gg;
            mx = fmaxf(mx, fabsf(gg));
        }
    }
    #pragma unroll
    for (int off = 16; off > 0; off >>= 1)
        mx = fmaxf(mx, __shfl_xor_sync(0xffffffff, mx, off));
    float clip = fmaxf(mx, 1e-5f);
    if (lane == 0) g_stok[token] = clip * (1.0f / 127.0f);
    float sc = 127.0f / clip;
    int pk[4];
    #pragma unroll
    for (int i = 0; i < 4; ++i) {
        int b0 = 0;
        #pragma unroll
        for (int e = 0; e < 4; ++e) {
            float q = rintf(vals[i * 4 + e] * sc);
            q = fminf(fmaxf(q, -128.0f), 127.0f);
            b0 |= ((int)q & 0xff) << (e * 8);
        }
        pk[i] = b0;
    }
    *(int4*)(g_xq + token * CC + c0) = make_int4(pk[0], pk[1], pk[2], pk[3]);
}

// ---------------- int8 proj GEMM via IMMA (exact): m=co, n=tok, vector epilogue ----
static __device__ __forceinline__ void ld_chunk_p(uint32_t abuf, uint32_t bbuf,
                                                  int idx, int co0, int tok0, int t) {
    const signed char* ga = g_wq + (size_t)co0 * 512 + idx * 128;   // A rows = co
    const signed char* gb = g_xq + (size_t)tok0 * 512 + idx * 128;  // B rows = tok
    for (int it = t; it < 1024; it += 256) {
        int row = it >> 3, c = it & 7;
        cp16(abuf + SWZ(row * 128 + c * 16), ga + (size_t)row * 512 + c * 16);
    }
    for (int it = t; it < 1024; it += 256) {
        int row = it >> 3, c = it & 7;
        cp16(bbuf + SWZ(row * 128 + c * 16), gb + (size_t)row * 512 + c * 16);
    }
}

__global__ __launch_bounds__(256) void proj_mma_kernel(const float* __restrict__ xres,
                                                       float* __restrict__ out) {
    extern __shared__ char dsm_raw[];
    char* base = (char*)((((size_t)dsm_raw) + 1023) & ~(size_t)1023);
    uint32_t sb = smem_u32(base);
    uint32_t ab[2] = { sb,             sb + 32768 };
    uint32_t bb[2] = { sb + 16384,     sb + 49152 };

    int t = threadIdx.x, wid = t >> 5, lane = t & 31;
    int co0  = blockIdx.x * 128;
    int tok0 = blockIdx.y * 128;
    int wco  = (wid & 1) * 64;     // warp covers 64 co (m)
    int wtok = (wid >> 1) * 32;    // warp covers 32 tokens (n)

    int acc[4][4][4];
    #pragma unroll
    for (int i = 0; i < 4; ++i)
        #pragma unroll
        for (int j = 0; j < 4; ++j)
            #pragma unroll
            for (int e = 0; e < 4; ++e) acc[i][j][e] = 0;

    int g = lane >> 3, r = lane & 7;
    uint32_t ao[4], aM[4], bo[2], bM[2];
    #pragma unroll
    for (int mt = 0; mt < 4; ++mt) {
        int row = wco + mt * 16 + (g & 1) * 8 + r;
        uint32_t o = row * 128 + (g >> 1) * 16;
        aM[mt] = (o >> 3) & 0x70; ao[mt] = o;
    }
    #pragma unroll
    for (int nt = 0; nt < 2; ++nt) {
        int row = wtok + nt * 16 + (g >> 1) * 8 + r;
        uint32_t o = row * 128 + (g & 1) * 16;
        bM[nt] = (o >> 3) & 0x70; bo[nt] = o;
    }

    ld_chunk_p(ab[0], bb[0], 0, co0, tok0, t);
    CP_COMMIT();

    for (int i = 0; i < 4; ++i) {
        int cur = i & 1;
        if (i + 1 < 4) {
            ld_chunk_p(ab[cur ^ 1], bb[cur ^ 1], i + 1, co0, tok0, t);
            CP_COMMIT();
            CP_WAIT1();
        } else {
            CP_WAIT0();
        }
        __syncthreads();

        uint32_t abase = ab[cur], bbase = bb[cur];
        #pragma unroll
        for (int ks = 0; ks < 4; ++ks) {
            uint32_t A[4][4], Bf[2][4];
            #pragma unroll
            for (int mt = 0; mt < 4; ++mt)
                LDSM_X4(A[mt][0], A[mt][1], A[mt][2], A[mt][3],
                        abase + (((ao[mt] + ks * 32)) ^ aM[mt]));
            #pragma unroll
            for (int nt = 0; nt < 2; ++nt)
                LDSM_X4(Bf[nt][0], Bf[nt][1], Bf[nt][2], Bf[nt][3],
                        bbase + (((bo[nt] + ks * 32)) ^ bM[nt]));
            #pragma unroll
            for (int mt = 0; mt < 4; ++mt)
                #pragma unroll
                for (int n8 = 0; n8 < 4; ++n8)
                    imma16832(acc[mt][n8], A[mt],
                              Bf[n8 >> 1][(n8 & 1) * 2], Bf[n8 >> 1][(n8 & 1) * 2 + 1]);
        }
        __syncthreads();
    }

    // epilogue: acc[mt][n8] = {(co,tok),(co,tok+1),(co+8,tok),(co+8,tok+1)}
    float wdq = g_wdq;
    #pragma unroll
    for (int n8 = 0; n8 < 4; ++n8) {
        int tok = tok0 + wtok + n8 * 8 + (lane & 3) * 2;
        float2 sp = *(const float2*)&g_stok[tok];
        float s0 = sp.x * wdq, s1 = sp.y * wdq;
        int b = tok >> 10, l = tok & 1023;
        #pragma unroll
        for (int mt = 0; mt < 4; ++mt) {
            int co = co0 + wco + mt * 16 + (lane >> 2);
            size_t base0 = (((size_t)b * CC + co) << 10) + l;
            size_t base1 = base0 + ((size_t)8 << 10);
            float2 r0 = *(const float2*)&xres[base0];
            float2 r1 = *(const float2*)&xres[base1];
            float2 o0, o1;
            o0.x = gelu_exact((float)acc[mt][n8][0] * s0) + r0.x;
            o0.y = gelu_exact((float)acc[mt][n8][1] * s1) + r0.y;
            o1.x = gelu_exact((float)acc[mt][n8][2] * s0) + r1.x;
            o1.y = gelu_exact((float)acc[mt][n8][3] * s1) + r1.y;
            *(float2*)&out[base0] = o0;
            *(float2*)&out[base1] = o1;
        }
    }
}

// ---------------- launch ----------------
extern "C" void kernel_launch(void* const* d_in, const int* in_sizes, int n_in,
                              void* d_out, int out_size) {
    (void)in_sizes; (void)n_in; (void)out_size;
    const float* x      = (const float*)d_in[0];   // [32,512,1024]
    const float* conv_w = (const float*)d_in[1];   // [512,512,3]
    const float* conv_b = (const float*)d_in[2];   // [512]
    const float* gamma  = (const float*)d_in[3];   // [512]
    const float* beta   = (const float*)d_in[4];   // [512]
    const float* proj_w = (const float*)d_in[5];   // [512,512]
    float* out = (float*)d_out;

    static int smem_set = 0;
    if (!smem_set) {
        cudaFuncSetAttribute(conv_mma_kernel, cudaFuncAttributeMaxDynamicSharedMemorySize, 66560);
        cudaFuncSetAttribute(proj_mma_kernel, cudaFuncAttributeMaxDynamicSharedMemorySize, 66560);
        smem_set = 1;
    }

    prep_part_kernel<<<64, 256>>>(proj_w);
    prep_fin_kernel<<<1, 64>>>();
    prep_quant_kernel<<<256, 256>>>(proj_w);

    pack_w_kernel<<<(CC * 1536 + 255) / 256, 256>>>(conv_w);
    pack_x_kernel<<<dim3(8, 8, 32), 256>>>(x);

    conv_mma_kernel<<<dim3(4, 256), 256, 66560>>>(conv_b);

    bn_part_kernel<<<64, 512>>>();
    bn_fin_kernel<<<1, 512>>>();
    quant_kernel<<<NN / 8, 256>>>(gamma, beta);

    proj_mma_kernel<<<dim3(4, 256), 256, 66560>>>(x, out);
}

// round 9
// speedup vs baseline: 2.3389x; 1.0565x over previous
#include <cuda_runtime.h>
#include <cuda_bf16.h>
#include <math.h>
#include <stdint.h>

#define BB 32
#define CC 512
#define LL 1024
#define NN (BB*LL)   /* 32768 tokens */
#define BROWS (BB * (LL + 2))   /* 32*1026 guard-row layout */

// ---------------- scratch (device globals; no allocation) ----------------
__device__ __align__(16) float        g_conv[(size_t)NN * CC];      // conv out [token][co] (67MB)
__device__ __align__(16) signed char  g_xq[(size_t)NN * CC];        // int8 activations [token][c]
__device__ __align__(16) float        g_stok[NN];                   // per-token dequant scale
__device__ __align__(16) float        g_mean[CC];
__device__ __align__(16) float        g_rstd[CC];
__device__ __align__(16) signed char  g_wq[CC * CC];                // ternary proj weights [o][c]
__device__ float                      g_wdq;                        // weight dequant scale
// conv GEMM operands, bf16 2-term split
__device__ __align__(16) __nv_bfloat16 g_wq2[(size_t)CC * 3072];    // weights [co][(split?1536:0)+tap*512+ci]
// activations: row = b*1026 + 1 + l (rows b*1026 and b*1026+1025 are zero guards)
__device__ __align__(16) __nv_bfloat16 g_bq[(size_t)BROWS * 1024];  // 67MB
// BN partial stats: one fp32 (sum, sumsq) slice per token-block (128 of them)
__device__ __align__(16) float g_psf[128 * CC];
__device__ __align__(16) float g_ps2f[128 * CC];
__device__ double g_wsum[64];

__device__ __forceinline__ float gelu_exact(float v) {
    return 0.5f * v * (1.0f + erff(v * 0.70710678118654752440f));
}

// ---------------- helpers ----------------
__device__ __forceinline__ uint32_t smem_u32(const void* p) {
    uint32_t a;
    asm("{ .reg .u64 t; cvta.to.shared.u64 t, %1; cvt.u32.u64 %0, t; }" : "=r"(a) : "l"(p));
    return a;
}
#define SWZ(o) ((o) ^ (((o) >> 3) & 0x70))

__device__ __forceinline__ void cp16(uint32_t dst, const void* src) {
    asm volatile("cp.async.cg.shared.global [%0], [%1], 16;" :: "r"(dst), "l"(src));
}
#define CP_COMMIT() asm volatile("cp.async.commit_group;" ::: "memory")
#define CP_WAIT0()  asm volatile("cp.async.wait_group 0;" ::: "memory")
#define CP_WAIT1()  asm volatile("cp.async.wait_group 1;" ::: "memory")

#define LDSM_X4(r0, r1, r2, r3, addr) \
    asm volatile("ldmatrix.sync.aligned.m8n8.x4.shared.b16 {%0,%1,%2,%3}, [%4];" \
        : "=r"(r0), "=r"(r1), "=r"(r2), "=r"(r3) : "r"(addr))

__device__ __forceinline__ void mma16816(float* d, const uint32_t* a, uint32_t b0, uint32_t b1) {
    asm volatile("mma.sync.aligned.m16n8k16.row.col.f32.bf16.bf16.f32 "
        "{%0,%1,%2,%3}, {%4,%5,%6,%7}, {%8,%9}, {%0,%1,%2,%3};"
        : "+f"(d[0]), "+f"(d[1]), "+f"(d[2]), "+f"(d[3])
        : "r"(a[0]), "r"(a[1]), "r"(a[2]), "r"(a[3]), "r"(b0), "r"(b1));
}

__device__ __forceinline__ void imma16832(int* d, const uint32_t* a, uint32_t b0, uint32_t b1) {
    asm volatile("mma.sync.aligned.m16n8k32.row.col.s32.s8.s8.s32 "
        "{%0,%1,%2,%3}, {%4,%5,%6,%7}, {%8,%9}, {%0,%1,%2,%3};"
        : "+r"(d[0]), "+r"(d[1]), "+r"(d[2]), "+r"(d[3])
        : "r"(a[0]), "r"(a[1]), "r"(a[2]), "r"(a[3]), "r"(b0), "r"(b1));
}

// ---------------- proj weight quant: partial -> fin -> quantize ----------------
__global__ void prep_part_kernel(const float* __restrict__ w) {
    __shared__ double red[256];
    int t = threadIdx.x;
    int base = blockIdx.x * 4096;
    double s = 0.0;
    #pragma unroll 4
    for (int i = t; i < 4096; i += 256) s += (double)fabsf(w[base + i]);
    red[t] = s; __syncthreads();
    for (int o = 128; o > 0; o >>= 1) { if (t < o) red[t] += red[t + o]; __syncthreads(); }
    if (t == 0) g_wsum[blockIdx.x] = red[0];
}
__global__ void prep_fin_kernel() {
    __shared__ double red[64];
    int t = threadIdx.x;
    red[t] = g_wsum[t]; __syncthreads();
    for (int o = 32; o > 0; o >>= 1) { if (t < o) red[t] += red[t + o]; __syncthreads(); }
    if (t == 0) {
        float mean = (float)(red[0] * (1.0 / (double)(CC * CC)));
        g_wdq = fmaxf(mean, 1e-5f);
    }
}
__global__ void prep_quant_kernel(const float* __restrict__ w) {
    int i = blockIdx.x * 1024 + threadIdx.x;
    float sc = 1.0f / g_wdq;
    #pragma unroll
    for (int e = 0; e < 4; ++e) {
        int idx = i + e * 256;
        float q = rintf(w[idx] * sc);
        q = fminf(fmaxf(q, -1.0f), 1.0f);
        g_wq[idx] = (signed char)(int)q;
    }
}

// ---------------- conv weight bf16-split pack ----------------
__global__ void pack_w_kernel(const float* __restrict__ w) {   // w: [co][ci][3]
    int idx = blockIdx.x * 256 + threadIdx.x;
    if (idx >= CC * 1536) return;
    int co = idx / 1536, r = idx % 1536;
    int tap = r / 512, ci = r % 512;
    float f = w[((size_t)co * CC + ci) * 3 + tap];
    __nv_bfloat16 h = __float2bfloat16(f);
    __nv_bfloat16 l = __float2bfloat16(f - __bfloat162float(h));
    g_wq2[(size_t)co * 3072 + r]        = h;
    g_wq2[(size_t)co * 3072 + 1536 + r] = l;
}

// ---------------- activation transpose + bf16-split pack (guard-row layout) --------
__global__ __launch_bounds__(256) void pack_x_kernel(const float* __restrict__ x) {
    __shared__ float xs[128 * 65];    // [l][ci], pad 65 -> conflict-free STS, ~2-way LDS
    int b   = blockIdx.z;
    int ci0 = blockIdx.y * 64;
    int l0  = blockIdx.x * 128;
    int t = threadIdx.x;

    for (int it = t; it < 64 * 128; it += 256) {
        int ci = it >> 7, c = it & 127;
        xs[c * 65 + ci] = x[((size_t)b * CC + ci0 + ci) * LL + l0 + c];
    }
    __syncthreads();

    for (int it = t; it < 1024; it += 256) {
        int tok = it >> 3, g = it & 7;
        __align__(16) __nv_bfloat16 hi[8], lo[8];
        #pragma unroll
        for (int e = 0; e < 8; ++e) {
            float f = xs[tok * 65 + g * 8 + e];
            __nv_bfloat16 h = __float2bfloat16(f);
            hi[e] = h;
            lo[e] = __float2bfloat16(f - __bfloat162float(h));
        }
        size_t row = (size_t)b * 1026 + 1 + l0 + tok;
        *(uint4*)(g_bq + row * 1024 + ci0 + g * 8)       = *(const uint4*)hi;
        *(uint4*)(g_bq + row * 1024 + 512 + ci0 + g * 8) = *(const uint4*)lo;
    }

    if (l0 == 0 && t < 16) {
        size_t row = (size_t)b * 1026;
        int col = (t >> 3) * 512 + ci0 + (t & 7) * 8;
        *(uint4*)(g_bq + row * 1024 + col) = make_uint4(0, 0, 0, 0);
    }
    if (l0 == (LL - 128) && t < 16) {
        size_t row = (size_t)b * 1026 + 1025;
        int col = (t >> 3) * 512 + ci0 + (t & 7) * 8;
        *(uint4*)(g_bq + row * 1024 + col) = make_uint4(0, 0, 0, 0);
    }
}

// ---------------- conv GEMM via mma.sync bf16 (3-pass split, fp32 acc) --------
// block tile 128 co x 256 tok; 8 warps of 64x64; fused BN partial stats.
static __device__ __forceinline__ void ld_chunk(uint32_t abuf, uint32_t bbuf,
                                                int idx, int co0, int browb, int t) {
    int p = idx / 24, ch = idx % 24;
    int tap = ch >> 3, cic = ch & 7;
    const __nv_bfloat16* ga = g_wq2 + (size_t)co0 * 3072 + ((p == 2) ? 1536 : 0) + ch * 64;
    const __nv_bfloat16* gb = g_bq + (size_t)(browb + tap) * 1024
                                   + ((p == 1) ? 512 : 0) + cic * 64;
    for (int it = t; it < 1024; it += 256) {
        int row = it >> 3, c = it & 7;
        cp16(abuf + SWZ(row * 128 + c * 16), ga + (size_t)row * 3072 + c * 8);
    }
    for (int it = t; it < 2048; it += 256) {
        int row = it >> 3, c = it & 7;
        cp16(bbuf + SWZ(row * 128 + c * 16), gb + (size_t)row * 1024 + c * 8);
    }
}

__global__ __launch_bounds__(256, 1) void conv_mma_kernel(const float* __restrict__ bias) {
    extern __shared__ char dsm_raw[];
    char* base = (char*)((((size_t)dsm_raw) + 1023) & ~(size_t)1023);
    uint32_t sb = smem_u32(base);
    uint32_t ab[2] = { sb,             sb + 16384 };
    uint32_t bb[2] = { sb + 32768,     sb + 65536 };
    __shared__ float bnred[8 * 64 * 2];   // [warp][co-in-64][sum/ssq]

    int t = threadIdx.x, wid = t >> 5, lane = t & 31;
    int co0 = blockIdx.x * 128;
    int tok0 = blockIdx.y * 256;
    int bidx = tok0 >> 10;
    int l0 = tok0 & 1023;
    int browb = bidx * 1026 + l0;
    int wco  = (wid & 1) * 64;         // warp covers 64 co (m)
    int wtok = (wid >> 1) * 64;        // warp covers 64 tokens (n)

    float acc[4][8][4];
    #pragma unroll
    for (int i = 0; i < 4; ++i)
        #pragma unroll
        for (int j = 0; j < 8; ++j)
            #pragma unroll
            for (int e = 0; e < 4; ++e) acc[i][j][e] = 0.0f;

    int g = lane >> 3, r = lane & 7;
    uint32_t ao[4], aM[4], bo[4], bM[4];
    #pragma unroll
    for (int mt = 0; mt < 4; ++mt) {
        int row = wco + mt * 16 + (g & 1) * 8 + r;
        uint32_t o = row * 128 + (g >> 1) * 16;
        aM[mt] = (o >> 3) & 0x70; ao[mt] = o;
    }
    #pragma unroll
    for (int nt = 0; nt < 4; ++nt) {
        int row = wtok + nt * 16 + (g >> 1) * 8 + r;
        uint32_t o = row * 128 + (g & 1) * 16;
        bM[nt] = (o >> 3) & 0x70; bo[nt] = o;
    }

    ld_chunk(ab[0], bb[0], 0, co0, browb, t);
    CP_COMMIT();

    for (int i = 0; i < 72; ++i) {
        int cur = i & 1;
        if (i + 1 < 72) {
            ld_chunk(ab[cur ^ 1], bb[cur ^ 1], i + 1, co0, browb, t);
            CP_COMMIT();
            CP_WAIT1();
        } else {
            CP_WAIT0();
        }
        __syncthreads();

        uint32_t abase = ab[cur], bbase = bb[cur];
        #pragma unroll
        for (int ks = 0; ks < 4; ++ks) {
            uint32_t Bf[4][4];
            #pragma unroll
            for (int nt = 0; nt < 4; ++nt)
                LDSM_X4(Bf[nt][0], Bf[nt][1], Bf[nt][2], Bf[nt][3],
                        bbase + (((bo[nt] + ks * 32)) ^ bM[nt]));
            #pragma unroll
            for (int mt = 0; mt < 4; ++mt) {
                uint32_t A[4];
                LDSM_X4(A[0], A[1], A[2], A[3],
                        abase + (((ao[mt] + ks * 32)) ^ aM[mt]));
                #pragma unroll
                for (int n8 = 0; n8 < 8; ++n8)
                    mma16816(acc[mt][n8], A,
                             Bf[n8 >> 1][(n8 & 1) * 2], Bf[n8 >> 1][(n8 & 1) * 2 + 1]);
            }
        }
        __syncthreads();
    }

    // ---- epilogue: bias add + store + fused BN partial sums ----
    float cs[4][2], cq[4][2];
    #pragma unroll
    for (int mt = 0; mt < 4; ++mt) { cs[mt][0] = cs[mt][1] = cq[mt][0] = cq[mt][1] = 0.0f; }

    #pragma unroll
    for (int mt = 0; mt < 4; ++mt) {
        int co = co0 + wco + mt * 16 + (lane >> 2);
        float bv0 = bias[co], bv1 = bias[co + 8];
        #pragma unroll
        for (int n8 = 0; n8 < 8; ++n8) {
            int tok = tok0 + wtok + n8 * 8 + (lane & 3) * 2;
            float v0 = acc[mt][n8][0] + bv0;
            float v1 = acc[mt][n8][1] + bv0;
            float v2 = acc[mt][n8][2] + bv1;
            float v3 = acc[mt][n8][3] + bv1;
            g_conv[(size_t)tok * CC + co]           = v0;
            g_conv[(size_t)(tok + 1) * CC + co]     = v1;
            g_conv[(size_t)tok * CC + co + 8]       = v2;
            g_conv[(size_t)(tok + 1) * CC + co + 8] = v3;
            cs[mt][0] += v0 + v1;  cq[mt][0] += v0 * v0 + v1 * v1;
            cs[mt][1] += v2 + v3;  cq[mt][1] += v2 * v2 + v3 * v3;
        }
    }
    // reduce over the 4 lanes sharing each co (lane&3 = token subgroups)
    #pragma unroll
    for (int off = 1; off <= 2; off <<= 1) {
        #pragma unroll
        for (int mt = 0; mt < 4; ++mt) {
            cs[mt][0] += __shfl_xor_sync(0xffffffff, cs[mt][0], off);
            cs[mt][1] += __shfl_xor_sync(0xffffffff, cs[mt][1], off);
            cq[mt][0] += __shfl_xor_sync(0xffffffff, cq[mt][0], off);
            cq[mt][1] += __shfl_xor_sync(0xffffffff, cq[mt][1], off);
        }
    }
    if ((lane & 3) == 0) {
        #pragma unroll
        for (int mt = 0; mt < 4; ++mt)
            #pragma unroll
            for (int h = 0; h < 2; ++h) {
                int ci = mt * 16 + (lane >> 2) + 8 * h;
                bnred[(wid * 64 + ci) * 2]     = cs[mt][h];
                bnred[(wid * 64 + ci) * 2 + 1] = cq[mt][h];
            }
    }
    __syncthreads();
    {
        int half = t >> 7, ci = (t >> 1) & 63, val = t & 1;
        float s = bnred[((half)     * 64 + ci) * 2 + val]
                + bnred[((half + 2) * 64 + ci) * 2 + val]
                + bnred[((half + 4) * 64 + ci) * 2 + val]
                + bnred[((half + 6) * 64 + ci) * 2 + val];
        int co = co0 + half * 64 + ci;
        if (val == 0) g_psf[blockIdx.y * CC + co]  = s;
        else          g_ps2f[blockIdx.y * CC + co] = s;
    }
}

// ---------------- BN finalize: deterministic double reduction over 128 slices ------
__global__ void bn_fin_kernel() {
    int co = threadIdx.x;
    double a = 0.0, b2 = 0.0;
    #pragma unroll 4
    for (int s = 0; s < 128; ++s) {
        a  += (double)g_psf[s * CC + co];
        b2 += (double)g_ps2f[s * CC + co];
    }
    double m = a / (double)NN;
    double var = b2 / (double)NN - m * m;
    g_mean[co] = (float)m;
    g_rstd[co] = (float)(1.0 / sqrt(var + 1e-5));
}

// ---------------- BN apply + GELU + per-token int8 quant (warp per token) ----------------
__global__ __launch_bounds__(256) void quant_kernel(const float* __restrict__ gamma,
                                                    const float* __restrict__ beta) {
    int t = threadIdx.x, w = t >> 5, lane = t & 31;
    size_t token = (size_t)blockIdx.x * 8 + w;
    int c0 = lane * 16;
    float vals[16];
    float mx = 0.0f;
    #pragma unroll
    for (int i = 0; i < 4; ++i) {
        float4 cv = *(const float4*)(g_conv + token * CC + c0 + i * 4);
        float4 m4 = *(const float4*)(g_mean + c0 + i * 4);
        float4 r4 = *(const float4*)(g_rstd + c0 + i * 4);
        float4 gm = *(const float4*)(gamma + c0 + i * 4);
        float4 bt = *(const float4*)(beta + c0 + i * 4);
        float a[4] = { (cv.x - m4.x) * r4.x * gm.x + bt.x,
                       (cv.y - m4.y) * r4.y * gm.y + bt.y,
                       (cv.z - m4.z) * r4.z * gm.z + bt.z,
                       (cv.w - m4.w) * r4.w * gm.w + bt.w };
        #pragma unroll
        for (int e = 0; e < 4; ++e) {
            float gg = gelu_exact(a[e]);
            vals[i * 4 + e] = gg;
            mx = fmaxf(mx, fabsf(gg));
        }
    }
    #pragma unroll
    for (int off = 16; off > 0; off >>= 1)
        mx = fmaxf(mx, __shfl_xor_sync(0xffffffff, mx, off));
    float clip = fmaxf(mx, 1e-5f);
    if (lane == 0) g_stok[token] = clip * (1.0f / 127.0f);
    float sc = 127.0f / clip;
    int pk[4];
    #pragma unroll
    for (int i = 0; i < 4; ++i) {
        int b0 = 0;
        #pragma unroll
        for (int e = 0; e < 4; ++e) {
            float q = rintf(vals[i * 4 + e] * sc);
            q = fminf(fmaxf(q, -128.0f), 127.0f);
            b0 |= ((int)q & 0xff) << (e * 8);
        }
        pk[i] = b0;
    }
    *(int4*)(g_xq + token * CC + c0) = make_int4(pk[0], pk[1], pk[2], pk[3]);
}

// ---------------- int8 proj GEMM via IMMA (exact): m=co, n=tok, vector epilogue ----
static __device__ __forceinline__ void ld_chunk_p(uint32_t abuf, uint32_t bbuf,
                                                  int idx, int co0, int tok0, int t) {
    const signed char* ga = g_wq + (size_t)co0 * 512 + idx * 128;   // A rows = co
    const signed char* gb = g_xq + (size_t)tok0 * 512 + idx * 128;  // B rows = tok
    for (int it = t; it < 1024; it += 256) {
        int row = it >> 3, c = it & 7;
        cp16(abuf + SWZ(row * 128 + c * 16), ga + (size_t)row * 512 + c * 16);
    }
    for (int it = t; it < 1024; it += 256) {
        int row = it >> 3, c = it & 7;
        cp16(bbuf + SWZ(row * 128 + c * 16), gb + (size_t)row * 512 + c * 16);
    }
}

__global__ __launch_bounds__(256) void proj_mma_kernel(const float* __restrict__ xres,
                                                       float* __restrict__ out) {
    extern __shared__ char dsm_raw[];
    char* base = (char*)((((size_t)dsm_raw) + 1023) & ~(size_t)1023);
    uint32_t sb = smem_u32(base);
    uint32_t ab[2] = { sb,             sb + 32768 };
    uint32_t bb[2] = { sb + 16384,     sb + 49152 };

    int t = threadIdx.x, wid = t >> 5, lane = t & 31;
    int co0  = blockIdx.x * 128;
    int tok0 = blockIdx.y * 128;
    int wco  = (wid & 1) * 64;     // warp covers 64 co (m)
    int wtok = (wid >> 1) * 32;    // warp covers 32 tokens (n)

    int acc[4][4][4];
    #pragma unroll
    for (int i = 0; i < 4; ++i)
        #pragma unroll
        for (int j = 0; j < 4; ++j)
            #pragma unroll
            for (int e = 0; e < 4; ++e) acc[i][j][e] = 0;

    int g = lane >> 3, r = lane & 7;
    uint32_t ao[4], aM[4], bo[2], bM[2];
    #pragma unroll
    for (int mt = 0; mt < 4; ++mt) {
        int row = wco + mt * 16 + (g & 1) * 8 + r;
        uint32_t o = row * 128 + (g >> 1) * 16;
        aM[mt] = (o >> 3) & 0x70; ao[mt] = o;
    }
    #pragma unroll
    for (int nt = 0; nt < 2; ++nt) {
        int row = wtok + nt * 16 + (g >> 1) * 8 + r;
        uint32_t o = row * 128 + (g & 1) * 16;
        bM[nt] = (o >> 3) & 0x70; bo[nt] = o;
    }

    ld_chunk_p(ab[0], bb[0], 0, co0, tok0, t);
    CP_COMMIT();

    for (int i = 0; i < 4; ++i) {
        int cur = i & 1;
        if (i + 1 < 4) {
            ld_chunk_p(ab[cur ^ 1], bb[cur ^ 1], i + 1, co0, tok0, t);
            CP_COMMIT();
            CP_WAIT1();
        } else {
            CP_WAIT0();
        }
        __syncthreads();

        uint32_t abase = ab[cur], bbase = bb[cur];
        #pragma unroll
        for (int ks = 0; ks < 4; ++ks) {
            uint32_t A[4][4], Bf[2][4];
            #pragma unroll
            for (int mt = 0; mt < 4; ++mt)
                LDSM_X4(A[mt][0], A[mt][1], A[mt][2], A[mt][3],
                        abase + (((ao[mt] + ks * 32)) ^ aM[mt]));
            #pragma unroll
            for (int nt = 0; nt < 2; ++nt)
                LDSM_X4(Bf[nt][0], Bf[nt][1], Bf[nt][2], Bf[nt][3],
                        bbase + (((bo[nt] + ks * 32)) ^ bM[nt]));
            #pragma unroll
            for (int mt = 0; mt < 4; ++mt)
                #pragma unroll
                for (int n8 = 0; n8 < 4; ++n8)
                    imma16832(acc[mt][n8], A[mt],
                              Bf[n8 >> 1][(n8 & 1) * 2], Bf[n8 >> 1][(n8 & 1) * 2 + 1]);
        }
        __syncthreads();
    }

    // epilogue: acc[mt][n8] = {(co,tok),(co,tok+1),(co+8,tok),(co+8,tok+1)}
    float wdq = g_wdq;
    #pragma unroll
    for (int n8 = 0; n8 < 4; ++n8) {
        int tok = tok0 + wtok + n8 * 8 + (lane & 3) * 2;
        float2 sp = *(const float2*)&g_stok[tok];
        float s0 = sp.x * wdq, s1 = sp.y * wdq;
        int b = tok >> 10, l = tok & 1023;
        #pragma unroll
        for (int mt = 0; mt < 4; ++mt) {
            int co = co0 + wco + mt * 16 + (lane >> 2);
            size_t base0 = (((size_t)b * CC + co) << 10) + l;
            size_t base1 = base0 + ((size_t)8 << 10);
            float2 r0 = *(const float2*)&xres[base0];
            float2 r1 = *(const float2*)&xres[base1];
            float2 o0, o1;
            o0.x = gelu_exact((float)acc[mt][n8][0] * s0) + r0.x;
            o0.y = gelu_exact((float)acc[mt][n8][1] * s1) + r0.y;
            o1.x = gelu_exact((float)acc[mt][n8][2] * s0) + r1.x;
            o1.y = gelu_exact((float)acc[mt][n8][3] * s1) + r1.y;
            *(float2*)&out[base0] = o0;
            *(float2*)&out[base1] = o1;
        }
    }
}

// ---------------- launch ----------------
extern "C" void kernel_launch(void* const* d_in, const int* in_sizes, int n_in,
                              void* d_out, int out_size) {
    (void)in_sizes; (void)n_in; (void)out_size;
    const float* x      = (const float*)d_in[0];   // [32,512,1024]
    const float* conv_w = (const float*)d_in[1];   // [512,512,3]
    const float* conv_b = (const float*)d_in[2];   // [512]
    const float* gamma  = (const float*)d_in[3];   // [512]
    const float* beta   = (const float*)d_in[4];   // [512]
    const float* proj_w = (const float*)d_in[5];   // [512,512]
    float* out = (float*)d_out;

    static int smem_set = 0;
    if (!smem_set) {
        cudaFuncSetAttribute(conv_mma_kernel, cudaFuncAttributeMaxDynamicSharedMemorySize, 99328);
        cudaFuncSetAttribute(proj_mma_kernel, cudaFuncAttributeMaxDynamicSharedMemorySize, 66560);
        smem_set = 1;
    }

    prep_part_kernel<<<64, 256>>>(proj_w);
    prep_fin_kernel<<<1, 64>>>();
    prep_quant_kernel<<<256, 256>>>(proj_w);

    pack_w_kernel<<<(CC * 1536 + 255) / 256, 256>>>(conv_w);
    pack_x_kernel<<<dim3(8, 8, 32), 256>>>(x);

    conv_mma_kernel<<<dim3(4, 128), 256, 99328>>>(conv_b);

    bn_fin_kernel<<<1, 512>>>();
    quant_kernel<<<NN / 8, 256>>>(gamma, beta);

    proj_mma_kernel<<<dim3(4, 256), 256, 66560>>>(x, out);
}